// round 6
// baseline (speedup 1.0000x reference)
#include <cuda_runtime.h>
#include <cuda_bf16.h>
#include <math.h>
#include <stdint.h>

#define Bq 8192
#define Fq 26
#define Dq 32
#define Vq 100000
#define Hq 128
#define NPAIR 351
#define KX1 352        // padded pairs (22 k-tiles of 16)
#define KPP_X1 176
#define Uq 400
#define KPP_CIN2 1664  // 3328/2
#define KPP_MLP1 416   // 832/2
#define KPP_MLP2 200   // 400/2

typedef unsigned u32;

// ---------------- scratch ----------------
__device__ float g_wsym[NPAIR * Hq];
__device__ int   g_pij[KX1];
__device__ __align__(16) u32 g_wBh[Hq * KPP_X1], g_wBl[Hq * KPP_X1];       // n-major [h][kp]
__device__ __align__(16) u32 g_Wc1h[Hq * KPP_CIN2], g_Wc1l[Hq * KPP_CIN2]; // [n][kp]
__device__ __align__(16) u32 g_W1h[512 * KPP_MLP1], g_W1l[512 * KPP_MLP1];
__device__ __align__(16) u32 g_W2h[512 * KPP_MLP2], g_W2l[512 * KPP_MLP2];
__device__ __align__(16) float g_embed[Bq * Fq * Dq];
__device__ __align__(16) u32 g_EAh[Bq * KPP_MLP1], g_EAl[Bq * KPP_MLP1];   // A [m][kp]
__device__ __align__(16) u32 g_SAh[(size_t)Bq * KPP_CIN2], g_SAl[(size_t)Bq * KPP_CIN2];
__device__ __align__(16) u32 g_H1h[Bq * KPP_MLP2], g_H1l[Bq * KPP_MLP2];
__device__ float g_lin[Bq];
__device__ float g_cin1[Bq * Hq];
__device__ float g_cin2a[Bq * Hq];
__device__ float g_cin2b[Bq * Hq];
__device__ float g_h2[Bq * Uq];

// ---------------- helpers ----------------
__device__ __forceinline__ void split2(float x, float y, u32 &hi, u32 &lo) {
    u32 xh = (u32)__bfloat16_as_ushort(__float2bfloat16_rn(x));
    u32 yh = (u32)__bfloat16_as_ushort(__float2bfloat16_rn(y));
    float xr = x - __uint_as_float(xh << 16);
    float yr = y - __uint_as_float(yh << 16);
    u32 xl = (u32)__bfloat16_as_ushort(__float2bfloat16_rn(xr));
    u32 yl = (u32)__bfloat16_as_ushort(__float2bfloat16_rn(yr));
    hi = xh | (yh << 16);
    lo = xl | (yl << 16);
}
__device__ __forceinline__ void mma16816(float c[4], const u32 a[4], u32 b0, u32 b1) {
    asm volatile(
        "mma.sync.aligned.m16n8k16.row.col.f32.bf16.bf16.f32 "
        "{%0,%1,%2,%3}, {%4,%5,%6,%7}, {%8,%9}, {%0,%1,%2,%3};"
        : "+f"(c[0]), "+f"(c[1]), "+f"(c[2]), "+f"(c[3])
        : "r"(a[0]), "r"(a[1]), "r"(a[2]), "r"(a[3]), "r"(b0), "r"(b1));
}
__device__ __forceinline__ void ldsm4(u32 &r0, u32 &r1, u32 &r2, u32 &r3, u32 addr) {
    asm volatile("ldmatrix.sync.aligned.m8n8.x4.shared.b16 {%0,%1,%2,%3}, [%4];"
                 : "=r"(r0), "=r"(r1), "=r"(r2), "=r"(r3) : "r"(addr));
}
__device__ __forceinline__ u32 smem_u32(const void* p) {
    u32 a;
    asm("{ .reg .u64 t; cvta.to.shared.u64 t, %1; cvt.u32.u64 %0, t; }"
        : "=r"(a) : "l"(p));
    return a;
}

// ---------------- prep: symmetrize W_cin0 ----------------
__global__ void prep_kernel(const float* __restrict__ W0) {
    int t = blockIdx.x * blockDim.x + threadIdx.x;
    if (t >= NPAIR && t < KX1) g_pij[t] = 0;
    if (t >= NPAIR * Hq) return;
    int p = t >> 7, h = t & 127;
    int i = 0, rem = p;
    while (rem >= Fq - i) { rem -= Fq - i; i++; }
    int j = i + rem;
    float w = W0[(i * Fq + j) * Hq + h];
    if (i != j) w += W0[(j * Fq + i) * Hq + h];
    g_wsym[t] = w;
    if (h == 0) g_pij[p] = i | (j << 8);
}

// ---------------- pack wsym -> n-major planes [h][176 kp] ----------------
__global__ void pack_wsymT() {
    int t = blockIdx.x * blockDim.x + threadIdx.x;
    if (t >= Hq * KPP_X1) return;
    int h = t / KPP_X1, kp = t % KPP_X1;
    float w0 = (2 * kp < NPAIR) ? g_wsym[(2 * kp) * Hq + h] : 0.f;
    float w1 = (2 * kp + 1 < NPAIR) ? g_wsym[(2 * kp + 1) * Hq + h] : 0.f;
    split2(w0, w1, g_wBh[t], g_wBl[t]);
}

// ---------------- pack weight W[K][N] -> n-major planes [Npad][Kpp] ----------------
__global__ void packB_T(const float* __restrict__ W, int Kreal, int Nreal,
                        int Kpp, int Npad, u32* __restrict__ Oh, u32* __restrict__ Ol) {
    int t = blockIdx.x * blockDim.x + threadIdx.x;
    if (t >= Npad * Kpp) return;
    int n = t / Kpp, kp = t % Kpp;
    float f0 = (n < Nreal && 2 * kp < Kreal) ? W[(size_t)(2 * kp) * Nreal + n] : 0.f;
    float f1 = (n < Nreal && 2 * kp + 1 < Kreal) ? W[(size_t)(2 * kp + 1) * Nreal + n] : 0.f;
    split2(f0, f1, Oh[t], Ol[t]);
}

// ---------------- gather: fp32 embed + packed A-plane for MLP1 ----------------
__global__ void gather_kernel(const int* __restrict__ idx, const float* __restrict__ E) {
    int e = blockIdx.x * blockDim.x + threadIdx.x;
    if (e >= Bq * Fq * (Dq / 4)) return;
    int q = e & 7;
    int r = e >> 3;
    int i = r % Fq;
    int b = r / Fq;
    int v = __ldg(&idx[b * Fq + i]);
    float4 val = __ldg((const float4*)(E + ((size_t)i * Vq + v) * Dq) + q);
    ((float4*)g_embed)[e] = val;
    int u = b * KPP_MLP1 + i * 16 + q * 2;
    split2(val.x, val.y, g_EAh[u], g_EAl[u]);
    split2(val.z, val.w, g_EAh[u + 1], g_EAl[u + 1]);
}

// ---------------- linear term ----------------
__global__ void lin_kernel(const int* __restrict__ idx, const float* __restrict__ w_lin,
                           const float* __restrict__ b_lin) {
    int b = blockIdx.x * blockDim.x + threadIdx.x;
    if (b >= Bq) return;
    float a = b_lin[0];
#pragma unroll
    for (int f = 0; f < Fq; f++) a += (float)idx[b * Fq + f] * w_lin[f];
    g_lin[b] = a;
}

// ---------------- fused x1 mma GEMM + cin1 + packed S ----------------
// block = 4 batch rows; M=128 (m=b4*32+d), N=128 (h), K=352 (22 tiles of 16).
// dyn smem u32 layout:
//   [0,6144)      A stages: (s*2+plane)*1536   (128 rows x pitch 12)
//   [6144,12288)  B stages: 6144 + (s*2+plane)*1536
//   [0,16896)     x1s overlay (float, pitch 132) -- used after mainloop
//   [16896,20224) sx (4*26*32 floats)
//   [20224,20576) spij
#define X1_DYN (20576 * 4)
__global__ __launch_bounds__(256, 2) void x1_kernel() {
    extern __shared__ u32 dsm[];
    float* sx  = (float*)(dsm + 16896);
    int* spij  = (int*)(dsm + 20224);
    int tid = threadIdx.x;
    int warp = tid >> 5, lane = tid & 31;
    int gid = lane >> 2, tg = lane & 3;
    int wm = warp & 3, wn = warp >> 2;

    const float* eb = g_embed + (size_t)blockIdx.x * 4 * Fq * Dq;
    for (int e = tid; e < 4 * Fq * Dq; e += 256) sx[e] = eb[e];
    for (int e = tid; e < KX1; e += 256) spij[e] = g_pij[e];

    float c[2][8][4];
#pragma unroll
    for (int mt = 0; mt < 2; mt++)
#pragma unroll
        for (int nt = 0; nt < 8; nt++)
#pragma unroll
            for (int r = 0; r < 4; r++) c[mt][nt][r] = 0.f;

    // ldmatrix lane offsets
    int la_off = ((lane & 7) + (lane & 8)) * 12 + ((lane & 16) >> 2);
    int lb_off = ((lane & 7) + ((lane & 16) >> 1)) * 12 + ((lane & 8) >> 1);
    u32 smbase = smem_u32(dsm);

    auto build = [&](int t, int s) {
        // B: 128 h x 8 kp from n-major planes
        {
            int n = tid >> 1, q = tid & 1;
            uint4 vh = *(const uint4*)&g_wBh[n * KPP_X1 + t * 8 + q * 4];
            uint4 vl = *(const uint4*)&g_wBl[n * KPP_X1 + t * 8 + q * 4];
            *(uint4*)&dsm[6144 + (s * 2 + 0) * 1536 + n * 12 + q * 4] = vh;
            *(uint4*)&dsm[6144 + (s * 2 + 1) * 1536 + n * 12 + q * 4] = vl;
        }
        // A: 128 m x 8 kp pair-products
        u32* ah = dsm + (s * 2 + 0) * 1536;
        u32* al = dsm + (s * 2 + 1) * 1536;
#pragma unroll
        for (int it = 0; it < 4; it++) {
            int idx = it * 256 + tid;
            int kp = idx >> 7, m = idx & 127;
            int b4 = m >> 5, d = m & 31;
            const float* sb = sx + b4 * (Fq * Dq) + d;
            int k0 = t * 16 + kp * 2;
            int q0 = spij[k0], q1 = spij[k0 + 1];
            float a0 = sb[(q0 & 255) * Dq] * sb[(q0 >> 8) * Dq];
            float a1 = sb[(q1 & 255) * Dq] * sb[(q1 >> 8) * Dq];
            u32 hi, lo;
            split2(a0, a1, hi, lo);
            ah[m * 12 + kp] = hi;
            al[m * 12 + kp] = lo;
        }
    };

    __syncthreads();      // sx/spij ready
    build(0, 0);

#pragma unroll 1
    for (int t = 0; t < 22; t++) {
        __syncthreads();
        int s = t & 1;
        u32 aBase = smbase + (s * 2) * 1536 * 4;
        u32 bBase = smbase + (6144 + s * 2 * 1536) * 4;
        u32 ah[2][4], al[2][4];
#pragma unroll
        for (int mt = 0; mt < 2; mt++) {
            u32 ad = aBase + ((wm * 32 + mt * 16) * 12 + la_off) * 4;
            ldsm4(ah[mt][0], ah[mt][1], ah[mt][2], ah[mt][3], ad);
            ldsm4(al[mt][0], al[mt][1], al[mt][2], al[mt][3], ad + 1536 * 4);
        }
#pragma unroll
        for (int np = 0; np < 4; np++) {
            u32 bd = bBase + ((wn * 64 + np * 16) * 12 + lb_off) * 4;
            u32 bh[4], bl[4];
            ldsm4(bh[0], bh[1], bh[2], bh[3], bd);
            ldsm4(bl[0], bl[1], bl[2], bl[3], bd + 1536 * 4);
#pragma unroll
            for (int mt = 0; mt < 2; mt++) {
                mma16816(c[mt][2 * np],     ah[mt], bh[0], bh[1]);
                mma16816(c[mt][2 * np],     ah[mt], bl[0], bl[1]);
                mma16816(c[mt][2 * np],     al[mt], bh[0], bh[1]);
                mma16816(c[mt][2 * np + 1], ah[mt], bh[2], bh[3]);
                mma16816(c[mt][2 * np + 1], ah[mt], bl[2], bl[3]);
                mma16816(c[mt][2 * np + 1], al[mt], bh[2], bh[3]);
            }
        }
        if (t + 1 < 22) build(t + 1, s ^ 1);
    }
    __syncthreads();

    // spill x1 tile to overlay smem
    float* x1s = (float*)dsm;
#pragma unroll
    for (int mt = 0; mt < 2; mt++) {
        int r0 = wm * 32 + mt * 16 + gid;
#pragma unroll
        for (int nt = 0; nt < 8; nt++) {
            int col = wn * 64 + nt * 8 + 2 * tg;
            *(float2*)&x1s[r0 * 132 + col]       = make_float2(c[mt][nt][0], c[mt][nt][1]);
            *(float2*)&x1s[(r0 + 8) * 132 + col] = make_float2(c[mt][nt][2], c[mt][nt][3]);
        }
    }
    __syncthreads();

    int bRow0 = blockIdx.x * 4;
    // cin1[b,h] = sum_d x1[b,d,h]
#pragma unroll
    for (int it = 0; it < 2; it++) {
        int o = it * 256 + tid;
        int b4 = o >> 7, h = o & 127;
        float a = 0.f;
#pragma unroll
        for (int d = 0; d < Dq; d++) a += x1s[(b4 * 32 + d) * 132 + h];
        g_cin1[(bRow0 + b4) * Hq + h] = a;
    }
    // S[b, i*128+h] packed -> cin2 A planes
#pragma unroll 1
    for (int it = 0; it < 7; it++) {
        int G = it * 256 + tid;
        if (G >= 4 * Fq * 16) break;
        int hp8 = G & 15;
        int rest = G >> 4;
        int i = rest % Fq, b4 = rest / Fq;
        const float* ex = sx + b4 * (Fq * Dq) + i * Dq;
        float v[8];
#pragma unroll
        for (int j = 0; j < 8; j++) v[j] = 0.f;
#pragma unroll
        for (int d = 0; d < Dq; d++) {
            float e = ex[d];
            const float4* xr = (const float4*)&x1s[(b4 * 32 + d) * 132 + hp8 * 8];
            float4 x0 = xr[0], x1v = xr[1];
            v[0] += e * x0.x;  v[1] += e * x0.y;  v[2] += e * x0.z;  v[3] += e * x0.w;
            v[4] += e * x1v.x; v[5] += e * x1v.y; v[6] += e * x1v.z; v[7] += e * x1v.w;
        }
        size_t u = (size_t)(bRow0 + b4) * KPP_CIN2 + i * 64 + hp8 * 4;
        u32 hi, lo;
#pragma unroll
        for (int j = 0; j < 4; j++) {
            split2(v[2 * j], v[2 * j + 1], hi, lo);
            g_SAh[u + j] = hi;
            g_SAl[u + j] = lo;
        }
    }
}

// ---------------- packed-plane GEMM via mma + ldmatrix ----------------
// C[m0..+128, n0..+128]; A planes [M][pitchA], B planes n-major [Npad][pitchB].
#define G_DYN (12288 * 4)
__global__ __launch_bounds__(256) void gemm_pk(
    const u32* __restrict__ Agh, const u32* __restrict__ Agl, int pitchA,
    const u32* __restrict__ Bgh, const u32* __restrict__ Bgl, int pitchB,
    int kpOff, int kblks,
    const float* __restrict__ bias, int Nreal, int relu,
    float* __restrict__ Cf, u32* __restrict__ Oh, u32* __restrict__ Ol, int pitchO)
{
    extern __shared__ u32 dsm[];
    int tid = threadIdx.x;
    int warp = tid >> 5, lane = tid & 31;
    int gid = lane >> 2, tg = lane & 3;
    int wm = warp & 3, wn = warp >> 2;
    int m0 = blockIdx.y * 128, n0 = blockIdx.x * 128;

    int srow = tid >> 1, sq = tid & 1;
    const u32* pAh = Agh + (size_t)(m0 + srow) * pitchA + kpOff + sq * 4;
    const u32* pAl = Agl + (size_t)(m0 + srow) * pitchA + kpOff + sq * 4;
    const u32* pBh = Bgh + (size_t)(n0 + srow) * pitchB + kpOff + sq * 4;
    const u32* pBl = Bgl + (size_t)(n0 + srow) * pitchB + kpOff + sq * 4;
    int sidx = srow * 12 + sq * 4;

    int la_off = ((lane & 7) + (lane & 8)) * 12 + ((lane & 16) >> 2);
    int lb_off = ((lane & 7) + ((lane & 16) >> 1)) * 12 + ((lane & 8) >> 1);
    u32 smbase = smem_u32(dsm);

    float c[2][8][4];
#pragma unroll
    for (int mt = 0; mt < 2; mt++)
#pragma unroll
        for (int nt = 0; nt < 8; nt++)
#pragma unroll
            for (int r = 0; r < 4; r++) c[mt][nt][r] = 0.f;

    // prologue: stage tile 0 into buf 0
    {
        uint4 xah = *(const uint4*)pAh;
        uint4 xal = *(const uint4*)pAl;
        uint4 xbh = *(const uint4*)pBh;
        uint4 xbl = *(const uint4*)pBl;
        *(uint4*)&dsm[0 * 1536 + sidx] = xah;
        *(uint4*)&dsm[1 * 1536 + sidx] = xal;
        *(uint4*)&dsm[6144 + 0 * 1536 + sidx] = xbh;
        *(uint4*)&dsm[6144 + 1 * 1536 + sidx] = xbl;
    }
    __syncthreads();
    int buf = 0;

#pragma unroll 1
    for (int t = 0; t < kblks; t++) {
        uint4 xah, xal, xbh, xbl;
        bool have = (t + 1 < kblks);
        if (have) {
            int o = (t + 1) * 8;
            xah = *(const uint4*)(pAh + o);
            xal = *(const uint4*)(pAl + o);
            xbh = *(const uint4*)(pBh + o);
            xbl = *(const uint4*)(pBl + o);
        }
        u32 aBase = smbase + (buf * 2) * 1536 * 4;
        u32 bBase = smbase + (6144 + buf * 2 * 1536) * 4;
        u32 ah[2][4], al[2][4];
#pragma unroll
        for (int mt = 0; mt < 2; mt++) {
            u32 ad = aBase + ((wm * 32 + mt * 16) * 12 + la_off) * 4;
            ldsm4(ah[mt][0], ah[mt][1], ah[mt][2], ah[mt][3], ad);
            ldsm4(al[mt][0], al[mt][1], al[mt][2], al[mt][3], ad + 1536 * 4);
        }
#pragma unroll
        for (int np = 0; np < 4; np++) {
            u32 bd = bBase + ((wn * 64 + np * 16) * 12 + lb_off) * 4;
            u32 bh[4], bl[4];
            ldsm4(bh[0], bh[1], bh[2], bh[3], bd);
            ldsm4(bl[0], bl[1], bl[2], bl[3], bd + 1536 * 4);
#pragma unroll
            for (int mt = 0; mt < 2; mt++) {
                mma16816(c[mt][2 * np],     ah[mt], bh[0], bh[1]);
                mma16816(c[mt][2 * np],     ah[mt], bl[0], bl[1]);
                mma16816(c[mt][2 * np],     al[mt], bh[0], bh[1]);
                mma16816(c[mt][2 * np + 1], ah[mt], bh[2], bh[3]);
                mma16816(c[mt][2 * np + 1], ah[mt], bl[2], bl[3]);
                mma16816(c[mt][2 * np + 1], al[mt], bh[2], bh[3]);
            }
        }
        if (have) {
            int nb = buf ^ 1;
            *(uint4*)&dsm[(nb * 2 + 0) * 1536 + sidx] = xah;
            *(uint4*)&dsm[(nb * 2 + 1) * 1536 + sidx] = xal;
            *(uint4*)&dsm[6144 + (nb * 2 + 0) * 1536 + sidx] = xbh;
            *(uint4*)&dsm[6144 + (nb * 2 + 1) * 1536 + sidx] = xbl;
            __syncthreads();
            buf = nb;
        }
    }

    // epilogue
#pragma unroll
    for (int mt = 0; mt < 2; mt++) {
        int r0 = m0 + wm * 32 + mt * 16 + gid;
#pragma unroll
        for (int nt = 0; nt < 8; nt++) {
            int col = n0 + wn * 64 + nt * 8 + 2 * tg;
            if (col >= Nreal) continue;
            float b0v = bias ? bias[col] : 0.f;
            float b1v = bias ? bias[col + 1] : 0.f;
            float v0 = c[mt][nt][0] + b0v, v1 = c[mt][nt][1] + b1v;
            float v2 = c[mt][nt][2] + b0v, v3 = c[mt][nt][3] + b1v;
            if (relu) {
                v0 = fmaxf(v0, 0.f); v1 = fmaxf(v1, 0.f);
                v2 = fmaxf(v2, 0.f); v3 = fmaxf(v3, 0.f);
            }
            if (Cf) {
                *(float2*)&Cf[(size_t)r0 * Nreal + col]       = make_float2(v0, v1);
                *(float2*)&Cf[(size_t)(r0 + 8) * Nreal + col] = make_float2(v2, v3);
            }
            if (Oh) {
                u32 hi, lo;
                split2(v0, v1, hi, lo);
                Oh[(size_t)r0 * pitchO + (col >> 1)] = hi;
                Ol[(size_t)r0 * pitchO + (col >> 1)] = lo;
                split2(v2, v3, hi, lo);
                Oh[(size_t)(r0 + 8) * pitchO + (col >> 1)] = hi;
                Ol[(size_t)(r0 + 8) * pitchO + (col >> 1)] = lo;
            }
        }
    }
}

// ---------------- final head ----------------
__global__ void final_kernel(const float* __restrict__ dense,
                             const float* __restrict__ w_out,
                             const float* __restrict__ b_out,
                             float* __restrict__ out) {
    int gt = blockIdx.x * blockDim.x + threadIdx.x;
    int b = gt >> 5, lane = gt & 31;
    if (b >= Bq) return;
    float a = 0.f;
    const float* c1 = g_cin1 + b * Hq;
    const float* c2a = g_cin2a + b * Hq;
    const float* c2b = g_cin2b + b * Hq;
    const float* hh = g_h2 + b * Uq;
    for (int t = lane; t < Hq; t += 32) a += c1[t] * w_out[1 + t];
    for (int t = lane; t < Hq; t += 32) a += (c2a[t] + c2b[t]) * w_out[1 + Hq + t];
    for (int t = lane; t < Uq; t += 32) a += hh[t] * w_out[1 + 2 * Hq + t];
    if (lane < 13) a += dense[b * 13 + lane] * w_out[1 + 2 * Hq + Uq + lane];
#pragma unroll
    for (int o = 16; o > 0; o >>= 1) a += __shfl_down_sync(0xffffffffu, a, o);
    if (lane == 0) {
        float tot = a + g_lin[b] * w_out[0] + b_out[0];
        float o;
        if (tot >= 0.f) { o = 1.f / (1.f + expf(-tot)); }
        else            { float e = expf(tot); o = e / (1.f + e); }
        out[b] = o;
    }
}

extern "C" void kernel_launch(void* const* d_in, const int* in_sizes, int n_in,
                              void* d_out, int out_size) {
    (void)in_sizes; (void)n_in; (void)out_size;
    const float* dense  = (const float*)d_in[0];
    const int*   sparse = (const int*)  d_in[1];
    const float* E      = (const float*)d_in[2];
    const float* W0     = (const float*)d_in[3];
    const float* Wc1    = (const float*)d_in[4];
    const float* W1     = (const float*)d_in[5];
    const float* b1     = (const float*)d_in[6];
    const float* W2     = (const float*)d_in[7];
    const float* b2     = (const float*)d_in[8];
    const float* w_lin  = (const float*)d_in[9];
    const float* b_lin  = (const float*)d_in[10];
    const float* w_out  = (const float*)d_in[11];
    const float* b_out  = (const float*)d_in[12];
    float* out = (float*)d_out;

    cudaFuncSetAttribute(x1_kernel, cudaFuncAttributeMaxDynamicSharedMemorySize, X1_DYN);
    cudaFuncSetAttribute(gemm_pk,  cudaFuncAttributeMaxDynamicSharedMemorySize, G_DYN);

    void *pWc1h, *pWc1l, *pW1h, *pW1l, *pW2h, *pW2l;
    void *pEAh, *pEAl, *pSAh, *pSAl, *pH1h, *pH1l, *pC2a, *pC2b, *pH2;
    cudaGetSymbolAddress(&pWc1h, g_Wc1h); cudaGetSymbolAddress(&pWc1l, g_Wc1l);
    cudaGetSymbolAddress(&pW1h, g_W1h);   cudaGetSymbolAddress(&pW1l, g_W1l);
    cudaGetSymbolAddress(&pW2h, g_W2h);   cudaGetSymbolAddress(&pW2l, g_W2l);
    cudaGetSymbolAddress(&pEAh, g_EAh);   cudaGetSymbolAddress(&pEAl, g_EAl);
    cudaGetSymbolAddress(&pSAh, g_SAh);   cudaGetSymbolAddress(&pSAl, g_SAl);
    cudaGetSymbolAddress(&pH1h, g_H1h);   cudaGetSymbolAddress(&pH1l, g_H1l);
    cudaGetSymbolAddress(&pC2a, g_cin2a); cudaGetSymbolAddress(&pC2b, g_cin2b);
    cudaGetSymbolAddress(&pH2, g_h2);

    // launches 1-5 (ncu -s 5 -c 1 captures launch #6 = x1_kernel)
    gather_kernel<<<(Bq * Fq * (Dq / 4) + 255) / 256, 256>>>(sparse, E);
    lin_kernel<<<(Bq + 255) / 256, 256>>>(sparse, w_lin, b_lin);
    prep_kernel<<<(NPAIR * Hq + 255) / 256, 256>>>(W0);
    pack_wsymT<<<(Hq * KPP_X1 + 255) / 256, 256>>>();
    packB_T<<<(Hq * KPP_CIN2 + 255) / 256, 256>>>(
        Wc1, Fq * Hq, Hq, KPP_CIN2, Hq, (u32*)pWc1h, (u32*)pWc1l);

    x1_kernel<<<Bq / 4, 256, X1_DYN>>>();     // launch #6 -> profiled

    packB_T<<<(512 * KPP_MLP1 + 255) / 256, 256>>>(
        W1, Fq * Dq, Uq, KPP_MLP1, 512, (u32*)pW1h, (u32*)pW1l);
    packB_T<<<(512 * KPP_MLP2 + 255) / 256, 256>>>(
        W2, Uq, Uq, KPP_MLP2, 512, (u32*)pW2h, (u32*)pW2l);

    // cin2 split-K x2: halves of K=3328 into separate buffers
    gemm_pk<<<dim3(1, Bq / 128), 256, G_DYN>>>(
        (const u32*)pSAh, (const u32*)pSAl, KPP_CIN2,
        (const u32*)pWc1h, (const u32*)pWc1l, KPP_CIN2,
        0, 104, nullptr, Hq, 0, (float*)pC2a, nullptr, nullptr, 0);
    gemm_pk<<<dim3(1, Bq / 128), 256, G_DYN>>>(
        (const u32*)pSAh, (const u32*)pSAl, KPP_CIN2,
        (const u32*)pWc1h, (const u32*)pWc1l, KPP_CIN2,
        832, 104, nullptr, Hq, 0, (float*)pC2b, nullptr, nullptr, 0);
    // h1 = relu(embed @ W1 + b1) -> packed planes
    gemm_pk<<<dim3(4, Bq / 128), 256, G_DYN>>>(
        (const u32*)pEAh, (const u32*)pEAl, KPP_MLP1,
        (const u32*)pW1h, (const u32*)pW1l, KPP_MLP1,
        0, 52, b1, Uq, 1, nullptr, (u32*)pH1h, (u32*)pH1l, KPP_MLP2);
    // h2 = relu(h1 @ W2 + b2)
    gemm_pk<<<dim3(4, Bq / 128), 256, G_DYN>>>(
        (const u32*)pH1h, (const u32*)pH1l, KPP_MLP2,
        (const u32*)pW2h, (const u32*)pW2l, KPP_MLP2,
        0, 25, b2, Uq, 1, (float*)pH2, nullptr, nullptr, 0);

    final_kernel<<<(Bq * 32 + 255) / 256, 256>>>(dense, w_out, b_out, out);
}

// round 7
// speedup vs baseline: 1.3115x; 1.3115x over previous
#include <cuda_runtime.h>
#include <cuda_bf16.h>
#include <math.h>
#include <stdint.h>

#define Bq 8192
#define Fq 26
#define Dq 32
#define Vq 100000
#define Hq 128
#define NPAIR 351
#define KPAD 352       // padded pair count (x1 mma K)
#define NKP  176       // KPAD/2 packed k-pairs
#define Uq 400
#define KP_CIN2 1664   // 3328/2
#define KP_SPLIT 832   // half of KP_CIN2
#define KP_MLP1 416    // 832/2
#define KP_MLP2 200    // 400/2

// ---------------- scratch (no cudaMalloc allowed) ----------------
__device__ float    g_wsym[NPAIR * Hq];
__device__ int      g_pij[KPAD];
__device__ __align__(16) unsigned g_whi[NKP * Hq];
__device__ __align__(16) unsigned g_wlo[NKP * Hq];
__device__ __align__(16) float    g_embed[Bq * Fq * Dq];
__device__ __align__(16) unsigned g_Ehi[Bq * KP_MLP1], g_Elo[Bq * KP_MLP1];
__device__ __align__(16) unsigned g_Shi[(size_t)Bq * KP_CIN2], g_Slo[(size_t)Bq * KP_CIN2];
__device__ __align__(16) unsigned g_Wc1hi[KP_CIN2 * Hq], g_Wc1lo[KP_CIN2 * Hq];
__device__ __align__(16) unsigned g_W1hi[KP_MLP1 * Uq], g_W1lo[KP_MLP1 * Uq];
__device__ __align__(16) unsigned g_W2hi[KP_MLP2 * Uq], g_W2lo[KP_MLP2 * Uq];
__device__ __align__(16) unsigned g_H1hi[Bq * KP_MLP2], g_H1lo[Bq * KP_MLP2];
__device__ float    g_lin[Bq];
__device__ float    g_cin1[Bq * Hq];
__device__ float    g_cin2s[2 * Bq * Hq];     // split-K partial sums
__device__ float    g_h2[Bq * Uq];

// ---------------- helpers ----------------
__device__ __forceinline__ void split2(float x, float y, unsigned &hi, unsigned &lo) {
    unsigned xh = (unsigned)__bfloat16_as_ushort(__float2bfloat16_rn(x));
    unsigned yh = (unsigned)__bfloat16_as_ushort(__float2bfloat16_rn(y));
    float xr = x - __uint_as_float(xh << 16);
    float yr = y - __uint_as_float(yh << 16);
    unsigned xl = (unsigned)__bfloat16_as_ushort(__float2bfloat16_rn(xr));
    unsigned yl = (unsigned)__bfloat16_as_ushort(__float2bfloat16_rn(yr));
    hi = xh | (yh << 16);
    lo = xl | (yl << 16);
}

__device__ __forceinline__ void mma16816(float c[4], const unsigned a[4],
                                         unsigned b0, unsigned b1) {
    asm volatile(
        "mma.sync.aligned.m16n8k16.row.col.f32.bf16.bf16.f32 "
        "{%0,%1,%2,%3}, {%4,%5,%6,%7}, {%8,%9}, {%0,%1,%2,%3};"
        : "+f"(c[0]), "+f"(c[1]), "+f"(c[2]), "+f"(c[3])
        : "r"(a[0]), "r"(a[1]), "r"(a[2]), "r"(a[3]), "r"(b0), "r"(b1));
}

// ---------------- prep1: symmetrize W_cin0 ----------------
__global__ void prep_kernel(const float* __restrict__ W0) {
    int t = blockIdx.x * blockDim.x + threadIdx.x;
    if (t == 0) g_pij[NPAIR] = 0;
    if (t >= NPAIR * Hq) return;
    int p = t >> 7, h = t & 127;
    int i = 0, rem = p;
    while (rem >= Fq - i) { rem -= Fq - i; i++; }
    int j = i + rem;
    float w = W0[(i * Fq + j) * Hq + h];
    if (i != j) w += W0[(j * Fq + i) * Hq + h];
    g_wsym[t] = w;
    if (h == 0) g_pij[p] = i | (j << 8);
}

// ---------------- prep2: bf16-split + k-pair-pack wsym ----------------
__global__ void prep2_kernel() {
    int t = blockIdx.x * blockDim.x + threadIdx.x;
    if (t >= NKP * Hq) return;
    int kp = t >> 7, h = t & 127;
    int p0 = 2 * kp, p1 = 2 * kp + 1;
    float w0 = (p0 < NPAIR) ? g_wsym[p0 * Hq + h] : 0.f;
    float w1 = (p1 < NPAIR) ? g_wsym[p1 * Hq + h] : 0.f;
    split2(w0, w1, g_whi[t], g_wlo[t]);
}

// ---------------- packB: fp32 [K][N] -> packed [K/2][N] u32 hi/lo ----------------
__global__ void packB_kernel(const float* __restrict__ B, unsigned* __restrict__ hi,
                             unsigned* __restrict__ lo, int Kp, int N) {
    int t = blockIdx.x * blockDim.x + threadIdx.x;
    if (t >= Kp * N) return;
    int kp = t / N, n = t % N;
    split2(B[(size_t)(2 * kp) * N + n], B[(size_t)(2 * kp + 1) * N + n], hi[t], lo[t]);
}

// ---------------- gather: fp32 embed + packed split for MLP1 ----------------
__global__ void gather_kernel(const int* __restrict__ idx, const float* __restrict__ E) {
    int e = blockIdx.x * blockDim.x + threadIdx.x;       // float4 index
    if (e >= Bq * Fq * (Dq / 4)) return;
    int q = e & 7;
    int r = e >> 3;
    int i = r % Fq;
    int b = r / Fq;
    int v = __ldg(&idx[b * Fq + i]);
    float4 val = __ldg((const float4*)(E + ((size_t)i * Vq + v) * Dq) + q);
    ((float4*)g_embed)[e] = val;
    int u = b * KP_MLP1 + (i * 8 + q) * 2;
    split2(val.x, val.y, g_Ehi[u],     g_Elo[u]);
    split2(val.z, val.w, g_Ehi[u + 1], g_Elo[u + 1]);
}

// ---------------- linear term ----------------
__global__ void lin_kernel(const int* __restrict__ idx, const float* __restrict__ w_lin,
                           const float* __restrict__ b_lin) {
    int b = blockIdx.x * blockDim.x + threadIdx.x;
    if (b >= Bq) return;
    float a = b_lin[0];
#pragma unroll
    for (int f = 0; f < Fq; f++) a += (float)idx[b * Fq + f] * w_lin[f];
    g_lin[b] = a;
}

// ---------------- fused x1 GEMM + cin1 + S (packed) ----------------
// block = 4 batch rows; M-tile 128 (m = bl*32+d), N = 128, K = 352 (22 tiles).
// dyn smem overlay:
//   [0, 20992)      A/B stages (mainloop only): Ahi 6144 | Alo 6144 | Bhi 4352 | Blo 4352
//   [0, 67584)      x1s spill (epilogue only, 128 x 132 fp32)
//   [67584, 80896)  sx  (4*26*32 fp32)
//   [80896, 82304)  spij
#define X1_SMEM 82304
__global__ __launch_bounds__(256) void x1s_mma_kernel() {
    extern __shared__ char dsm[];
    unsigned* Ahi  = (unsigned*)(dsm + 0);         // 128*12 u32
    unsigned* Alo  = (unsigned*)(dsm + 6144);
    unsigned* Bhi  = (unsigned*)(dsm + 12288);     // 8*136 u32
    unsigned* Blo  = (unsigned*)(dsm + 16640);
    float*    x1s  = (float*)(dsm + 0);            // overlay (epilogue)
    float*    sx   = (float*)(dsm + 67584);
    int*      spij = (int*)(dsm + 80896);

    int tid  = threadIdx.x;
    int warp = tid >> 5, lane = tid & 31;
    int gid  = lane >> 2, tg = lane & 3;
    int wm   = warp & 3, wn = warp >> 2;

    const float* eb = g_embed + (size_t)blockIdx.x * 4 * Fq * Dq;
    for (int e = tid; e < 4 * Fq * Dq; e += 256) sx[e] = eb[e];
    for (int e = tid; e < KPAD; e += 256) spij[e] = g_pij[e];

    float c[2][8][4];
#pragma unroll
    for (int mt = 0; mt < 2; mt++)
#pragma unroll
        for (int nt = 0; nt < 8; nt++)
#pragma unroll
            for (int r = 0; r < 4; r++) c[mt][nt][r] = 0.f;

    __syncthreads();

#pragma unroll 1
    for (int t = 0; t < 22; t++) {
#pragma unroll
        for (int it = 0; it < 4; it++) {      // build A tile 128 x 8 kp
            int idx = it * 256 + tid;
            int kp = idx >> 7, m = idx & 127;
            int bl = m >> 5, d = m & 31;
            int k0 = t * 16 + kp * 2;
            int pij0 = spij[k0], pij1 = spij[k0 + 1];
            const float* sb = sx + bl * (Fq * Dq) + d;
            float a0 = sb[(pij0 & 255) * Dq] * sb[(pij0 >> 8) * Dq];
            float a1 = sb[(pij1 & 255) * Dq] * sb[(pij1 >> 8) * Dq];
            split2(a0, a1, Ahi[m * 12 + kp], Alo[m * 12 + kp]);
        }
#pragma unroll
        for (int it = 0; it < 4; it++) {      // B tile from prepacked wsym
            int idx = it * 256 + tid;
            int kp = idx >> 7, n = idx & 127;
            int g = (t * 8 + kp) * Hq + n;
            Bhi[kp * 136 + n] = g_whi[g];
            Blo[kp * 136 + n] = g_wlo[g];
        }
        __syncthreads();

        unsigned ah[2][4], al[2][4];
#pragma unroll
        for (int mt = 0; mt < 2; mt++) {
            int mb = wm * 32 + mt * 16;
            ah[mt][0] = Ahi[(mb + gid) * 12 + tg];         al[mt][0] = Alo[(mb + gid) * 12 + tg];
            ah[mt][1] = Ahi[(mb + gid + 8) * 12 + tg];     al[mt][1] = Alo[(mb + gid + 8) * 12 + tg];
            ah[mt][2] = Ahi[(mb + gid) * 12 + tg + 4];     al[mt][2] = Alo[(mb + gid) * 12 + tg + 4];
            ah[mt][3] = Ahi[(mb + gid + 8) * 12 + tg + 4]; al[mt][3] = Alo[(mb + gid + 8) * 12 + tg + 4];
        }
#pragma unroll
        for (int nt = 0; nt < 8; nt++) {
            int nb = wn * 64 + nt * 8;
            unsigned bh0 = Bhi[tg * 136 + nb + gid], bh1 = Bhi[(tg + 4) * 136 + nb + gid];
            unsigned bl0 = Blo[tg * 136 + nb + gid], bl1 = Blo[(tg + 4) * 136 + nb + gid];
#pragma unroll
            for (int mt = 0; mt < 2; mt++) {
                mma16816(c[mt][nt], ah[mt], bh0, bh1);
                mma16816(c[mt][nt], ah[mt], bl0, bl1);
                mma16816(c[mt][nt], al[mt], bh0, bh1);
            }
        }
        __syncthreads();
    }

    // spill x1 tile (128 x 128) to overlay smem
#pragma unroll
    for (int mt = 0; mt < 2; mt++) {
        int r0 = wm * 32 + mt * 16 + gid;
#pragma unroll
        for (int nt = 0; nt < 8; nt++) {
            int col = wn * 64 + nt * 8 + 2 * tg;
            *(float2*)&x1s[r0 * 132 + col]       = make_float2(c[mt][nt][0], c[mt][nt][1]);
            *(float2*)&x1s[(r0 + 8) * 132 + col] = make_float2(c[mt][nt][2], c[mt][nt][3]);
        }
    }
    __syncthreads();

    int bRow0 = blockIdx.x * 4;

    // cin1[b,h] = sum_d x1[b,d,h]
#pragma unroll
    for (int it = 0; it < 2; it++) {
        int o = tid + it * 256;
        int b4 = o >> 7, h = o & 127;
        float a = 0.f;
#pragma unroll
        for (int d = 0; d < Dq; d++) a += x1s[(b4 * 32 + d) * 132 + h];
        g_cin1[(bRow0 + b4) * Hq + h] = a;
    }

    // S[b,i,h] packed: 4*26*64 u32-pairs, 26 per thread
#pragma unroll 1
    for (int it = 0; it < 26; it++) {
        int o = tid + it * 256;
        int hp = o & 63;
        int rest = o >> 6;
        int i = rest % Fq, b4 = rest / Fq;
        const float* ex = sx + b4 * (Fq * Dq) + i * Dq;
        float s0 = 0.f, s1 = 0.f;
#pragma unroll
        for (int d = 0; d < Dq; d++) {
            float e = ex[d];
            float2 xv = *(const float2*)&x1s[(b4 * 32 + d) * 132 + 2 * hp];
            s0 += e * xv.x;
            s1 += e * xv.y;
        }
        unsigned hi, lo;
        split2(s0, s1, hi, lo);
        size_t u = (size_t)(bRow0 + b4) * KP_CIN2 + i * 64 + hp;
        g_Shi[u] = hi;
        g_Slo[u] = lo;
    }
}

// ---------------- packed GEMM with optional split-K (blockIdx.z) ----------------
// BM=128, BN=128, BK=16 (8 kp); 256 thr; wm 0..3 x 32 rows, wn 0..1 x 64 cols.
// A [M][pitchA] row-major packed; B [KpTotal][N] k-major packed.
// blockIdx.z selects K-segment [z*kpSeg, (z+1)*kpSeg) and output plane Cf + z*M*N.
__global__ __launch_bounds__(256) void gemm_pk(
    const unsigned* __restrict__ Agh, const unsigned* __restrict__ Agl, int pitchA,
    const unsigned* __restrict__ Bgh, const unsigned* __restrict__ Bgl, int N,
    int kpSeg, int Mtot,
    const float* __restrict__ bias, int relu,
    float* __restrict__ Cf, unsigned* __restrict__ Ch, unsigned* __restrict__ Cl)
{
    __shared__ __align__(16) unsigned sAh[2][128 * 12], sAl[2][128 * 12];
    __shared__ __align__(16) unsigned sBh[2][8 * 132],  sBl[2][8 * 132];

    int tid  = threadIdx.x;
    int warp = tid >> 5, lane = tid & 31;
    int gid  = lane >> 2, tg = lane & 3;
    int wm   = warp & 3, wn = warp >> 2;
    int m0 = blockIdx.y * 128, n0 = blockIdx.x * 128;
    int kpOff = blockIdx.z * kpSeg;
    if (Cf) Cf += (size_t)blockIdx.z * Mtot * N;

    int am = tid >> 1, ahalf = tid & 1;
    int bkp = tid >> 5, bn4 = tid & 31;
    int bcol = n0 + bn4 * 4;

    float c[2][8][4];
#pragma unroll
    for (int mt = 0; mt < 2; mt++)
#pragma unroll
        for (int nt = 0; nt < 8; nt++)
#pragma unroll
            for (int r = 0; r < 4; r++) c[mt][nt][r] = 0.f;

    int T = kpSeg >> 3;
    {
        uint4 xah = *(const uint4*)&Agh[(size_t)(m0 + am) * pitchA + kpOff + ahalf * 4];
        uint4 xal = *(const uint4*)&Agl[(size_t)(m0 + am) * pitchA + kpOff + ahalf * 4];
        uint4 xbh = make_uint4(0, 0, 0, 0), xbl = make_uint4(0, 0, 0, 0);
        if (bcol < N) {
            xbh = *(const uint4*)&Bgh[(size_t)(kpOff + bkp) * N + bcol];
            xbl = *(const uint4*)&Bgl[(size_t)(kpOff + bkp) * N + bcol];
        }
        *(uint4*)&sAh[0][am * 12 + ahalf * 4] = xah;
        *(uint4*)&sAl[0][am * 12 + ahalf * 4] = xal;
        *(uint4*)&sBh[0][bkp * 132 + bn4 * 4] = xbh;
        *(uint4*)&sBl[0][bkp * 132 + bn4 * 4] = xbl;
    }
    __syncthreads();
    int buf = 0;

#pragma unroll 1
    for (int t = 0; t < T; t++) {
        uint4 xah, xal, xbh, xbl;
        bool have = (t + 1 < T);
        if (have) {
            int k0p = kpOff + (t + 1) * 8;
            xah = *(const uint4*)&Agh[(size_t)(m0 + am) * pitchA + k0p + ahalf * 4];
            xal = *(const uint4*)&Agl[(size_t)(m0 + am) * pitchA + k0p + ahalf * 4];
            xbh = make_uint4(0, 0, 0, 0); xbl = make_uint4(0, 0, 0, 0);
            if (bcol < N) {
                xbh = *(const uint4*)&Bgh[(size_t)(k0p + bkp) * N + bcol];
                xbl = *(const uint4*)&Bgl[(size_t)(k0p + bkp) * N + bcol];
            }
        }

        const unsigned* Ah = sAh[buf]; const unsigned* Al = sAl[buf];
        const unsigned* Bh = sBh[buf]; const unsigned* Bl = sBl[buf];
        unsigned ah[2][4], al[2][4];
#pragma unroll
        for (int mt = 0; mt < 2; mt++) {
            int mb = wm * 32 + mt * 16;
            ah[mt][0] = Ah[(mb + gid) * 12 + tg];         al[mt][0] = Al[(mb + gid) * 12 + tg];
            ah[mt][1] = Ah[(mb + gid + 8) * 12 + tg];     al[mt][1] = Al[(mb + gid + 8) * 12 + tg];
            ah[mt][2] = Ah[(mb + gid) * 12 + tg + 4];     al[mt][2] = Al[(mb + gid) * 12 + tg + 4];
            ah[mt][3] = Ah[(mb + gid + 8) * 12 + tg + 4]; al[mt][3] = Al[(mb + gid + 8) * 12 + tg + 4];
        }
#pragma unroll
        for (int nt = 0; nt < 8; nt++) {
            int nb = wn * 64 + nt * 8;
            unsigned bh0 = Bh[tg * 132 + nb + gid], bh1 = Bh[(tg + 4) * 132 + nb + gid];
            unsigned bl0 = Bl[tg * 132 + nb + gid], bl1 = Bl[(tg + 4) * 132 + nb + gid];
#pragma unroll
            for (int mt = 0; mt < 2; mt++) {
                mma16816(c[mt][nt], ah[mt], bh0, bh1);
                mma16816(c[mt][nt], ah[mt], bl0, bl1);
                mma16816(c[mt][nt], al[mt], bh0, bh1);
            }
        }

        if (have) {
            int nb2 = buf ^ 1;
            *(uint4*)&sAh[nb2][am * 12 + ahalf * 4] = xah;
            *(uint4*)&sAl[nb2][am * 12 + ahalf * 4] = xal;
            *(uint4*)&sBh[nb2][bkp * 132 + bn4 * 4] = xbh;
            *(uint4*)&sBl[nb2][bkp * 132 + bn4 * 4] = xbl;
            __syncthreads();
            buf = nb2;
        }
    }

    // epilogue
    int Np = N >> 1;
#pragma unroll
    for (int mt = 0; mt < 2; mt++) {
        int r0 = m0 + wm * 32 + mt * 16 + gid;
#pragma unroll
        for (int nt = 0; nt < 8; nt++) {
            int col = n0 + wn * 64 + nt * 8 + 2 * tg;
            if (col >= N) continue;
            float b0v = bias ? bias[col] : 0.f;
            float b1v = bias ? bias[col + 1] : 0.f;
            float v0 = c[mt][nt][0] + b0v, v1 = c[mt][nt][1] + b1v;
            float v2 = c[mt][nt][2] + b0v, v3 = c[mt][nt][3] + b1v;
            if (relu) {
                v0 = fmaxf(v0, 0.f); v1 = fmaxf(v1, 0.f);
                v2 = fmaxf(v2, 0.f); v3 = fmaxf(v3, 0.f);
            }
            if (Cf) {
                *(float2*)&Cf[(size_t)r0 * N + col]       = make_float2(v0, v1);
                *(float2*)&Cf[(size_t)(r0 + 8) * N + col] = make_float2(v2, v3);
            }
            if (Ch) {
                unsigned hi, lo;
                split2(v0, v1, hi, lo);
                g_H1hi[(size_t)r0 * Np + (col >> 1)] = hi;
                g_H1lo[(size_t)r0 * Np + (col >> 1)] = lo;
                split2(v2, v3, hi, lo);
                g_H1hi[(size_t)(r0 + 8) * Np + (col >> 1)] = hi;
                g_H1lo[(size_t)(r0 + 8) * Np + (col >> 1)] = lo;
            }
        }
    }
    (void)Cl;
}

// ---------------- final head ----------------
__global__ void final_kernel(const float* __restrict__ dense,
                             const float* __restrict__ w_out,
                             const float* __restrict__ b_out,
                             float* __restrict__ out) {
    int gt = blockIdx.x * blockDim.x + threadIdx.x;
    int b = gt >> 5, lane = gt & 31;
    if (b >= Bq) return;
    float a = 0.f;
    const float* c1 = g_cin1 + b * Hq;
    const float* c2a = g_cin2s + b * Hq;
    const float* c2b = g_cin2s + Bq * Hq + b * Hq;
    const float* hh = g_h2 + b * Uq;
    for (int t = lane; t < Hq; t += 32) a += c1[t] * w_out[1 + t];
    for (int t = lane; t < Hq; t += 32) a += (c2a[t] + c2b[t]) * w_out[1 + Hq + t];
    for (int t = lane; t < Uq; t += 32) a += hh[t] * w_out[1 + 2 * Hq + t];
    if (lane < 13) a += dense[b * 13 + lane] * w_out[1 + 2 * Hq + Uq + lane];
#pragma unroll
    for (int o = 16; o > 0; o >>= 1) a += __shfl_down_sync(0xffffffffu, a, o);
    if (lane == 0) {
        float tot = a + g_lin[b] * w_out[0] + b_out[0];
        float o;
        if (tot >= 0.f) { o = 1.f / (1.f + expf(-tot)); }
        else            { float e = expf(tot); o = e / (1.f + e); }
        out[b] = o;
    }
}

extern "C" void kernel_launch(void* const* d_in, const int* in_sizes, int n_in,
                              void* d_out, int out_size) {
    (void)in_sizes; (void)n_in; (void)out_size;
    const float* dense  = (const float*)d_in[0];
    const int*   sparse = (const int*)  d_in[1];
    const float* E      = (const float*)d_in[2];
    const float* W0     = (const float*)d_in[3];
    const float* Wc1    = (const float*)d_in[4];
    const float* W1     = (const float*)d_in[5];
    const float* b1     = (const float*)d_in[6];
    const float* W2     = (const float*)d_in[7];
    const float* b2     = (const float*)d_in[8];
    const float* w_lin  = (const float*)d_in[9];
    const float* b_lin  = (const float*)d_in[10];
    const float* w_out  = (const float*)d_in[11];
    const float* b_out  = (const float*)d_in[12];
    float* out = (float*)d_out;

    static int smem_set = 0;
    if (!smem_set) {
        cudaFuncSetAttribute(x1s_mma_kernel,
                             cudaFuncAttributeMaxDynamicSharedMemorySize, X1_SMEM);
        smem_set = 1;
    }

    void *pShi, *pSlo, *pEhi, *pElo, *pWc1hi, *pWc1lo, *pW1hi, *pW1lo,
         *pW2hi, *pW2lo, *pH1hi, *pH1lo, *pC2, *pH2;
    cudaGetSymbolAddress(&pShi, g_Shi);   cudaGetSymbolAddress(&pSlo, g_Slo);
    cudaGetSymbolAddress(&pEhi, g_Ehi);   cudaGetSymbolAddress(&pElo, g_Elo);
    cudaGetSymbolAddress(&pWc1hi, g_Wc1hi); cudaGetSymbolAddress(&pWc1lo, g_Wc1lo);
    cudaGetSymbolAddress(&pW1hi, g_W1hi); cudaGetSymbolAddress(&pW1lo, g_W1lo);
    cudaGetSymbolAddress(&pW2hi, g_W2hi); cudaGetSymbolAddress(&pW2lo, g_W2lo);
    cudaGetSymbolAddress(&pH1hi, g_H1hi); cudaGetSymbolAddress(&pH1lo, g_H1lo);
    cudaGetSymbolAddress(&pC2, g_cin2s);  cudaGetSymbolAddress(&pH2, g_h2);

    // launches 1-3 are x1's dependencies; x1 is launch #4 (ncu captures #4)
    prep_kernel<<<(NPAIR * Hq + 255) / 256, 256>>>(W0);
    prep2_kernel<<<(NKP * Hq + 255) / 256, 256>>>();
    gather_kernel<<<(Bq * Fq * (Dq / 4) + 255) / 256, 256>>>(sparse, E);

    x1s_mma_kernel<<<Bq / 4, 256, X1_SMEM>>>();

    lin_kernel<<<(Bq + 255) / 256, 256>>>(sparse, w_lin, b_lin);
    packB_kernel<<<(KP_CIN2 * Hq + 255) / 256, 256>>>(Wc1, (unsigned*)pWc1hi, (unsigned*)pWc1lo, KP_CIN2, Hq);
    packB_kernel<<<(KP_MLP1 * Uq + 255) / 256, 256>>>(W1, (unsigned*)pW1hi, (unsigned*)pW1lo, KP_MLP1, Uq);
    packB_kernel<<<(KP_MLP2 * Uq + 255) / 256, 256>>>(W2, (unsigned*)pW2hi, (unsigned*)pW2lo, KP_MLP2, Uq);

    // cin2 = S @ Wc1, split-K x2 in one launch (grid.z = 2, 128 blocks)
    gemm_pk<<<dim3(1, Bq / 128, 2), 256>>>(
        (const unsigned*)pShi, (const unsigned*)pSlo, KP_CIN2,
        (const unsigned*)pWc1hi, (const unsigned*)pWc1lo, Hq,
        KP_SPLIT, Bq, nullptr, 0, (float*)pC2, nullptr, nullptr);
    // h1 = relu(embed @ W1 + b1) -> packed split only
    gemm_pk<<<dim3((Uq + 127) / 128, Bq / 128, 1), 256>>>(
        (const unsigned*)pEhi, (const unsigned*)pElo, KP_MLP1,
        (const unsigned*)pW1hi, (const unsigned*)pW1lo, Uq,
        KP_MLP1, Bq, b1, 1, nullptr, (unsigned*)pH1hi, (unsigned*)pH1lo);
    // h2 = relu(h1 @ W2 + b2) -> fp32
    gemm_pk<<<dim3((Uq + 127) / 128, Bq / 128, 1), 256>>>(
        (const unsigned*)pH1hi, (const unsigned*)pH1lo, KP_MLP2,
        (const unsigned*)pW2hi, (const unsigned*)pW2lo, Uq,
        KP_MLP2, Bq, b2, 1, (float*)pH2, nullptr, nullptr);

    final_kernel<<<(Bq * 32 + 255) / 256, 256>>>(dense, w_out, b_out, out);
}

// round 9
// speedup vs baseline: 1.3557x; 1.0337x over previous
#include <cuda_runtime.h>
#include <cuda_bf16.h>
#include <math.h>
#include <stdint.h>

#define Bq 8192
#define Fq 26
#define Dq 32
#define Vq 100000
#define Hq 128
#define NPAIR 351
#define KPAD 352       // padded pair count (x1 mma K)
#define KPP_X1 176     // KPAD/2
#define Uq 400
#define KP_CIN2 1664   // 3328/2
#define KP_SPLIT 832   // half of KP_CIN2
#define KP_MLP1 416    // 832/2
#define KP_MLP2 200    // 400/2

typedef unsigned u32;

// ---------------- scratch (no cudaMalloc allowed) ----------------
__device__ float g_wsym[NPAIR * Hq];
__device__ int   g_pij[KPAD];
__device__ __align__(16) u32 g_wBh[Hq * KPP_X1], g_wBl[Hq * KPP_X1];         // n-major [h][kp]
__device__ __align__(16) float g_embed[Bq * Fq * Dq];
__device__ __align__(16) u32 g_Ehi[Bq * KP_MLP1], g_Elo[Bq * KP_MLP1];       // A [m][kp]
__device__ __align__(16) u32 g_Shi[(size_t)Bq * KP_CIN2], g_Slo[(size_t)Bq * KP_CIN2];
__device__ __align__(16) u32 g_Wc1hi[Hq * KP_CIN2], g_Wc1lo[Hq * KP_CIN2];   // n-major [n][kp]
__device__ __align__(16) u32 g_W1hi[512 * KP_MLP1], g_W1lo[512 * KP_MLP1];   // n-major padded
__device__ __align__(16) u32 g_W2hi[512 * KP_MLP2], g_W2lo[512 * KP_MLP2];
__device__ __align__(16) u32 g_H1hi[Bq * KP_MLP2], g_H1lo[Bq * KP_MLP2];     // A [m][kp]
__device__ float g_lin[Bq];
__device__ float g_cin1[Bq * Hq];
__device__ float g_cin2s[2 * Bq * Hq];
__device__ float g_h2[Bq * Uq];

// ---------------- helpers ----------------
__device__ __forceinline__ void split2(float x, float y, u32 &hi, u32 &lo) {
    u32 xh = (u32)__bfloat16_as_ushort(__float2bfloat16_rn(x));
    u32 yh = (u32)__bfloat16_as_ushort(__float2bfloat16_rn(y));
    float xr = x - __uint_as_float(xh << 16);
    float yr = y - __uint_as_float(yh << 16);
    u32 xl = (u32)__bfloat16_as_ushort(__float2bfloat16_rn(xr));
    u32 yl = (u32)__bfloat16_as_ushort(__float2bfloat16_rn(yr));
    hi = xh | (yh << 16);
    lo = xl | (yl << 16);
}
__device__ __forceinline__ void mma16816(float c[4], const u32 a[4], u32 b0, u32 b1) {
    asm volatile(
        "mma.sync.aligned.m16n8k16.row.col.f32.bf16.bf16.f32 "
        "{%0,%1,%2,%3}, {%4,%5,%6,%7}, {%8,%9}, {%0,%1,%2,%3};"
        : "+f"(c[0]), "+f"(c[1]), "+f"(c[2]), "+f"(c[3])
        : "r"(a[0]), "r"(a[1]), "r"(a[2]), "r"(a[3]), "r"(b0), "r"(b1));
}
__device__ __forceinline__ void ldsm4(u32 &r0, u32 &r1, u32 &r2, u32 &r3, u32 addr) {
    asm volatile("ldmatrix.sync.aligned.m8n8.x4.shared.b16 {%0,%1,%2,%3}, [%4];"
                 : "=r"(r0), "=r"(r1), "=r"(r2), "=r"(r3) : "r"(addr));
}
__device__ __forceinline__ u32 smem_u32(const void* p) {
    u32 a;
    asm("{ .reg .u64 t; cvta.to.shared.u64 t, %1; cvt.u32.u64 %0, t; }"
        : "=r"(a) : "l"(p));
    return a;
}

// ---------------- prep1: symmetrize W_cin0 ----------------
__global__ void prep_kernel(const float* __restrict__ W0) {
    int t = blockIdx.x * blockDim.x + threadIdx.x;
    if (t == 0) g_pij[NPAIR] = 0;
    if (t >= NPAIR * Hq) return;
    int p = t >> 7, h = t & 127;
    int i = 0, rem = p;
    while (rem >= Fq - i) { rem -= Fq - i; i++; }
    int j = i + rem;
    float w = W0[(i * Fq + j) * Hq + h];
    if (i != j) w += W0[(j * Fq + i) * Hq + h];
    g_wsym[t] = w;
    if (h == 0) g_pij[p] = i | (j << 8);
}

// ---------------- prep2: wsym -> n-major packed planes [h][kp] ----------------
__global__ void pack_wsymT() {
    int t = blockIdx.x * blockDim.x + threadIdx.x;
    if (t >= Hq * KPP_X1) return;
    int h = t / KPP_X1, kp = t % KPP_X1;
    float w0 = (2 * kp < NPAIR) ? g_wsym[(2 * kp) * Hq + h] : 0.f;
    float w1 = (2 * kp + 1 < NPAIR) ? g_wsym[(2 * kp + 1) * Hq + h] : 0.f;
    split2(w0, w1, g_wBh[t], g_wBl[t]);
}

// ---------------- packB_T: fp32 W[K][N] -> n-major packed [Npad][Kpp] ----------------
__global__ void packB_T(const float* __restrict__ W, int Kreal, int Nreal,
                        int Kpp, int Npad, u32* __restrict__ Oh, u32* __restrict__ Ol) {
    int t = blockIdx.x * blockDim.x + threadIdx.x;
    if (t >= Npad * Kpp) return;
    int n = t / Kpp, kp = t % Kpp;
    float f0 = (n < Nreal && 2 * kp < Kreal) ? W[(size_t)(2 * kp) * Nreal + n] : 0.f;
    float f1 = (n < Nreal && 2 * kp + 1 < Kreal) ? W[(size_t)(2 * kp + 1) * Nreal + n] : 0.f;
    split2(f0, f1, Oh[t], Ol[t]);
}

// ---------------- gather: fp32 embed + packed split for MLP1 ----------------
__global__ void gather_kernel(const int* __restrict__ idx, const float* __restrict__ E) {
    int e = blockIdx.x * blockDim.x + threadIdx.x;
    if (e >= Bq * Fq * (Dq / 4)) return;
    int q = e & 7;
    int r = e >> 3;
    int i = r % Fq;
    int b = r / Fq;
    int v = __ldg(&idx[b * Fq + i]);
    float4 val = __ldg((const float4*)(E + ((size_t)i * Vq + v) * Dq) + q);
    ((float4*)g_embed)[e] = val;
    int u = b * KP_MLP1 + (i * 8 + q) * 2;
    split2(val.x, val.y, g_Ehi[u],     g_Elo[u]);
    split2(val.z, val.w, g_Ehi[u + 1], g_Elo[u + 1]);
}

// ---------------- linear term ----------------
__global__ void lin_kernel(const int* __restrict__ idx, const float* __restrict__ w_lin,
                           const float* __restrict__ b_lin) {
    int b = blockIdx.x * blockDim.x + threadIdx.x;
    if (b >= Bq) return;
    float a = b_lin[0];
#pragma unroll
    for (int f = 0; f < Fq; f++) a += (float)idx[b * Fq + f] * w_lin[f];
    g_lin[b] = a;
}

// ---------------- fused x1 GEMM + cin1 + S (packed) ----------------
// block = 4 batch rows; M = 128 (m = bl*32+d), N = 128, K = 352 (22 tiles).
// dyn smem overlay (bytes):
//   [0,6144) Ahi | [6144,12288) Alo | [12288,18432) Bhi(n-major) | [18432,24576) Blo
//   [0,67584)      x1s spill overlay (epilogue)
//   [67584,80896)  sx  | [80896,82304) spij
#define X1_SMEM 82304
__global__ __launch_bounds__(256) void x1s_mma_kernel() {
    extern __shared__ char dsm_c[];
    u32*   Ahi  = (u32*)(dsm_c + 0);          // [128 m][12]
    u32*   Alo  = (u32*)(dsm_c + 6144);
    u32*   Bh_s = (u32*)(dsm_c + 12288);      // [128 n][12]
    u32*   Bl_s = (u32*)(dsm_c + 18432);
    float* x1s  = (float*)(dsm_c + 0);        // overlay
    float* sx   = (float*)(dsm_c + 67584);
    int*   spij = (int*)(dsm_c + 80896);

    int tid  = threadIdx.x;
    int warp = tid >> 5, lane = tid & 31;
    int gid  = lane >> 2, tg = lane & 3;
    int wm   = warp & 3, wn = warp >> 2;

    const float* eb = g_embed + (size_t)blockIdx.x * 4 * Fq * Dq;
    for (int e = tid; e < 4 * Fq * Dq; e += 256) sx[e] = eb[e];
    for (int e = tid; e < KPAD; e += 256) spij[e] = g_pij[e];

    float c[2][8][4];
#pragma unroll
    for (int mt = 0; mt < 2; mt++)
#pragma unroll
        for (int nt = 0; nt < 8; nt++)
#pragma unroll
            for (int r = 0; r < 4; r++) c[mt][nt][r] = 0.f;

    // ldmatrix per-lane offsets (u32 units, pitch 12)
    int la_off = ((lane & 7) + (lane & 8)) * 12 + ((lane & 16) >> 2);
    int lb_off = ((lane & 7) + ((lane & 16) >> 1)) * 12 + ((lane & 8) >> 1);
    u32 smA = smem_u32(dsm_c);
    u32 smB = smA + 12288;

    int bn = tid >> 1, bq = tid & 1;

    __syncthreads();

#pragma unroll 1
    for (int t = 0; t < 22; t++) {
#pragma unroll
        for (int it = 0; it < 4; it++) {      // build A tile 128 m x 8 kp
            int idx = it * 256 + tid;
            int kp = idx >> 7, m = idx & 127;
            int bl = m >> 5, d = m & 31;
            int k0 = t * 16 + kp * 2;
            int pij0 = spij[k0], pij1 = spij[k0 + 1];
            const float* sb = sx + bl * (Fq * Dq) + d;
            float a0 = sb[(pij0 & 255) * Dq] * sb[(pij0 >> 8) * Dq];
            float a1 = sb[(pij1 & 255) * Dq] * sb[(pij1 >> 8) * Dq];
            split2(a0, a1, Ahi[m * 12 + kp], Alo[m * 12 + kp]);
        }
        {   // stage B tile (n-major): 128 n x 8 kp, 1 uint4/thread/plane
            uint4 vh = *(const uint4*)&g_wBh[bn * KPP_X1 + t * 8 + bq * 4];
            uint4 vl = *(const uint4*)&g_wBl[bn * KPP_X1 + t * 8 + bq * 4];
            *(uint4*)&Bh_s[bn * 12 + bq * 4] = vh;
            *(uint4*)&Bl_s[bn * 12 + bq * 4] = vl;
        }
        __syncthreads();

        u32 ah[2][4], al[2][4];
#pragma unroll
        for (int mt = 0; mt < 2; mt++) {
            u32 ad = smA + ((wm * 32 + mt * 16) * 12 + la_off) * 4;
            ldsm4(ah[mt][0], ah[mt][1], ah[mt][2], ah[mt][3], ad);
            ldsm4(al[mt][0], al[mt][1], al[mt][2], al[mt][3], ad + 6144);
        }
#pragma unroll
        for (int np = 0; np < 4; np++) {
            u32 bd = smB + ((wn * 64 + np * 16) * 12 + lb_off) * 4;
            u32 bh[4], bl[4];
            ldsm4(bh[0], bh[1], bh[2], bh[3], bd);
            ldsm4(bl[0], bl[1], bl[2], bl[3], bd + 6144);
#pragma unroll
            for (int mt = 0; mt < 2; mt++) {
                mma16816(c[mt][2 * np],     ah[mt], bh[0], bh[1]);
                mma16816(c[mt][2 * np],     ah[mt], bl[0], bl[1]);
                mma16816(c[mt][2 * np],     al[mt], bh[0], bh[1]);
                mma16816(c[mt][2 * np + 1], ah[mt], bh[2], bh[3]);
                mma16816(c[mt][2 * np + 1], ah[mt], bl[2], bl[3]);
                mma16816(c[mt][2 * np + 1], al[mt], bh[2], bh[3]);
            }
        }
        __syncthreads();
    }

    // spill x1 tile (128 x 128) to overlay smem
#pragma unroll
    for (int mt = 0; mt < 2; mt++) {
        int r0 = wm * 32 + mt * 16 + gid;
#pragma unroll
        for (int nt = 0; nt < 8; nt++) {
            int col = wn * 64 + nt * 8 + 2 * tg;
            *(float2*)&x1s[r0 * 132 + col]       = make_float2(c[mt][nt][0], c[mt][nt][1]);
            *(float2*)&x1s[(r0 + 8) * 132 + col] = make_float2(c[mt][nt][2], c[mt][nt][3]);
        }
    }
    __syncthreads();

    int bRow0 = blockIdx.x * 4;

    // cin1[b,h] = sum_d x1[b,d,h]
#pragma unroll
    for (int it = 0; it < 2; it++) {
        int o = tid + it * 256;
        int b4 = o >> 7, h = o & 127;
        float a = 0.f;
#pragma unroll
        for (int d = 0; d < Dq; d++) a += x1s[(b4 * 32 + d) * 132 + h];
        g_cin1[(bRow0 + b4) * Hq + h] = a;
    }

    // S[b,i,h] packed: 4*26*64 u32-pairs, 26 per thread
#pragma unroll 1
    for (int it = 0; it < 26; it++) {
        int o = tid + it * 256;
        int hp = o & 63;
        int rest = o >> 6;
        int i = rest % Fq, b4 = rest / Fq;
        const float* ex = sx + b4 * (Fq * Dq) + i * Dq;
        float s0 = 0.f, s1 = 0.f;
#pragma unroll
        for (int d = 0; d < Dq; d++) {
            float e = ex[d];
            float2 xv = *(const float2*)&x1s[(b4 * 32 + d) * 132 + 2 * hp];
            s0 += e * xv.x;
            s1 += e * xv.y;
        }
        u32 hi, lo;
        split2(s0, s1, hi, lo);
        size_t u = (size_t)(bRow0 + b4) * KP_CIN2 + i * 64 + hp;
        g_Shi[u] = hi;
        g_Slo[u] = lo;
    }
}

// ---------------- packed GEMM (ldmatrix + split-K via blockIdx.z) ----------------
// BM=128, BN=128, BK=16 (8 kp); A [M][pitchA] row-major, B n-major [Npad][pitchB].
// dyn smem (u32): sAh buf*1536 | sAl 3072+buf*1536 | sBh 6144+buf*1536 | sBl 9216+buf*1536
#define G_SMEM 49152
__global__ __launch_bounds__(256) void gemm_pk(
    const u32* __restrict__ Agh, const u32* __restrict__ Agl, int pitchA,
    const u32* __restrict__ Bgh, const u32* __restrict__ Bgl, int pitchB, int N,
    int kpSeg, int Mtot,
    const float* __restrict__ bias, int relu,
    float* __restrict__ Cf, u32* __restrict__ Ch, u32* __restrict__ Cl)
{
    extern __shared__ char dsm_c[];
    u32* dsm = (u32*)dsm_c;
    int tid  = threadIdx.x;
    int warp = tid >> 5, lane = tid & 31;
    int gid  = lane >> 2, tg = lane & 3;
    int wm   = warp & 3, wn = warp >> 2;
    int m0 = blockIdx.y * 128, n0 = blockIdx.x * 128;
    int kpOff = blockIdx.z * kpSeg;
    if (Cf) Cf += (size_t)blockIdx.z * Mtot * N;

    int sr = tid >> 1, sq = tid & 1;
    const u32* pAh = Agh + (size_t)(m0 + sr) * pitchA + kpOff + sq * 4;
    const u32* pAl = Agl + (size_t)(m0 + sr) * pitchA + kpOff + sq * 4;
    const u32* pBh = Bgh + (size_t)(n0 + sr) * pitchB + kpOff + sq * 4;
    const u32* pBl = Bgl + (size_t)(n0 + sr) * pitchB + kpOff + sq * 4;
    int sidx = sr * 12 + sq * 4;

    int la_off = ((lane & 7) + (lane & 8)) * 12 + ((lane & 16) >> 2);
    int lb_off = ((lane & 7) + ((lane & 16) >> 1)) * 12 + ((lane & 8) >> 1);
    u32 smbase = smem_u32(dsm_c);

    float c[2][8][4];
#pragma unroll
    for (int mt = 0; mt < 2; mt++)
#pragma unroll
        for (int nt = 0; nt < 8; nt++)
#pragma unroll
            for (int r = 0; r < 4; r++) c[mt][nt][r] = 0.f;

    int T = kpSeg >> 3;
    {   // prologue: stage tile 0 into buf 0
        uint4 xah = *(const uint4*)pAh;
        uint4 xal = *(const uint4*)pAl;
        uint4 xbh = *(const uint4*)pBh;
        uint4 xbl = *(const uint4*)pBl;
        *(uint4*)&dsm[sidx]        = xah;
        *(uint4*)&dsm[3072 + sidx] = xal;
        *(uint4*)&dsm[6144 + sidx] = xbh;
        *(uint4*)&dsm[9216 + sidx] = xbl;
    }
    __syncthreads();
    int buf = 0;

#pragma unroll 1
    for (int t = 0; t < T; t++) {
        uint4 xah, xal, xbh, xbl;
        bool have = (t + 1 < T);
        if (have) {
            int o = (t + 1) * 8;
            xah = *(const uint4*)(pAh + o);
            xal = *(const uint4*)(pAl + o);
            xbh = *(const uint4*)(pBh + o);
            xbl = *(const uint4*)(pBl + o);
        }

        u32 aBase = smbase + (buf * 1536) * 4;
        u32 bBase = smbase + ((6144 + buf * 1536)) * 4;
        u32 ah[2][4], al[2][4];
#pragma unroll
        for (int mt = 0; mt < 2; mt++) {
            u32 ad = aBase + ((wm * 32 + mt * 16) * 12 + la_off) * 4;
            ldsm4(ah[mt][0], ah[mt][1], ah[mt][2], ah[mt][3], ad);
            ldsm4(al[mt][0], al[mt][1], al[mt][2], al[mt][3], ad + 3072 * 4);
        }
#pragma unroll
        for (int np = 0; np < 4; np++) {
            u32 bd = bBase + ((wn * 64 + np * 16) * 12 + lb_off) * 4;
            u32 bh[4], bl[4];
            ldsm4(bh[0], bh[1], bh[2], bh[3], bd);
            ldsm4(bl[0], bl[1], bl[2], bl[3], bd + 3072 * 4);
#pragma unroll
            for (int mt = 0; mt < 2; mt++) {
                mma16816(c[mt][2 * np],     ah[mt], bh[0], bh[1]);
                mma16816(c[mt][2 * np],     ah[mt], bl[0], bl[1]);
                mma16816(c[mt][2 * np],     al[mt], bh[0], bh[1]);
                mma16816(c[mt][2 * np + 1], ah[mt], bh[2], bh[3]);
                mma16816(c[mt][2 * np + 1], ah[mt], bl[2], bl[3]);
                mma16816(c[mt][2 * np + 1], al[mt], bh[2], bh[3]);
            }
        }

        if (have) {
            int nb = buf ^ 1;
            *(uint4*)&dsm[nb * 1536 + sidx]        = xah;
            *(uint4*)&dsm[3072 + nb * 1536 + sidx] = xal;
            *(uint4*)&dsm[6144 + nb * 1536 + sidx] = xbh;
            *(uint4*)&dsm[9216 + nb * 1536 + sidx] = xbl;
            __syncthreads();
            buf = nb;
        }
    }

    // epilogue
    int Np = N >> 1;
#pragma unroll
    for (int mt = 0; mt < 2; mt++) {
        int r0 = m0 + wm * 32 + mt * 16 + gid;
#pragma unroll
        for (int nt = 0; nt < 8; nt++) {
            int col = n0 + wn * 64 + nt * 8 + 2 * tg;
            if (col >= N) continue;
            float b0v = bias ? bias[col] : 0.f;
            float b1v = bias ? bias[col + 1] : 0.f;
            float v0 = c[mt][nt][0] + b0v, v1 = c[mt][nt][1] + b1v;
            float v2 = c[mt][nt][2] + b0v, v3 = c[mt][nt][3] + b1v;
            if (relu) {
                v0 = fmaxf(v0, 0.f); v1 = fmaxf(v1, 0.f);
                v2 = fmaxf(v2, 0.f); v3 = fmaxf(v3, 0.f);
            }
            if (Cf) {
                *(float2*)&Cf[(size_t)r0 * N + col]       = make_float2(v0, v1);
                *(float2*)&Cf[(size_t)(r0 + 8) * N + col] = make_float2(v2, v3);
            }
            if (Ch) {
                u32 hi, lo;
                split2(v0, v1, hi, lo);
                Ch[(size_t)r0 * Np + (col >> 1)] = hi;
                Cl[(size_t)r0 * Np + (col >> 1)] = lo;
                split2(v2, v3, hi, lo);
                Ch[(size_t)(r0 + 8) * Np + (col >> 1)] = hi;
                Cl[(size_t)(r0 + 8) * Np + (col >> 1)] = lo;
            }
        }
    }
}

// ---------------- final head ----------------
__global__ void final_kernel(const float* __restrict__ dense,
                             const float* __restrict__ w_out,
                             const float* __restrict__ b_out,
                             float* __restrict__ out) {
    int gt = blockIdx.x * blockDim.x + threadIdx.x;
    int b = gt >> 5, lane = gt & 31;
    if (b >= Bq) return;
    float a = 0.f;
    const float* c1 = g_cin1 + b * Hq;
    const float* c2a = g_cin2s + b * Hq;
    const float* c2b = g_cin2s + Bq * Hq + b * Hq;
    const float* hh = g_h2 + b * Uq;
    for (int t = lane; t < Hq; t += 32) a += c1[t] * w_out[1 + t];
    for (int t = lane; t < Hq; t += 32) a += (c2a[t] + c2b[t]) * w_out[1 + Hq + t];
    for (int t = lane; t < Uq; t += 32) a += hh[t] * w_out[1 + 2 * Hq + t];
    if (lane < 13) a += dense[b * 13 + lane] * w_out[1 + 2 * Hq + Uq + lane];
#pragma unroll
    for (int o = 16; o > 0; o >>= 1) a += __shfl_down_sync(0xffffffffu, a, o);
    if (lane == 0) {
        float tot = a + g_lin[b] * w_out[0] + b_out[0];
        float o;
        if (tot >= 0.f) { o = 1.f / (1.f + expf(-tot)); }
        else            { float e = expf(tot); o = e / (1.f + e); }
        out[b] = o;
    }
}

extern "C" void kernel_launch(void* const* d_in, const int* in_sizes, int n_in,
                              void* d_out, int out_size) {
    (void)in_sizes; (void)n_in; (void)out_size;
    const float* dense  = (const float*)d_in[0];
    const int*   sparse = (const int*)  d_in[1];
    const float* E      = (const float*)d_in[2];
    const float* W0     = (const float*)d_in[3];
    const float* Wc1    = (const float*)d_in[4];
    const float* W1     = (const float*)d_in[5];
    const float* b1     = (const float*)d_in[6];
    const float* W2     = (const float*)d_in[7];
    const float* b2     = (const float*)d_in[8];
    const float* w_lin  = (const float*)d_in[9];
    const float* b_lin  = (const float*)d_in[10];
    const float* w_out  = (const float*)d_in[11];
    const float* b_out  = (const float*)d_in[12];
    float* out = (float*)d_out;

    static int smem_set = 0;
    if (!smem_set) {
        cudaFuncSetAttribute(x1s_mma_kernel,
                             cudaFuncAttributeMaxDynamicSharedMemorySize, X1_SMEM);
        cudaFuncSetAttribute(gemm_pk,
                             cudaFuncAttributeMaxDynamicSharedMemorySize, G_SMEM);
        smem_set = 1;
    }

    void *pShi, *pSlo, *pEhi, *pElo, *pWc1hi, *pWc1lo, *pW1hi, *pW1lo,
         *pW2hi, *pW2lo, *pH1hi, *pH1lo, *pC2, *pH2;
    cudaGetSymbolAddress(&pShi, g_Shi);   cudaGetSymbolAddress(&pSlo, g_Slo);
    cudaGetSymbolAddress(&pEhi, g_Ehi);   cudaGetSymbolAddress(&pElo, g_Elo);
    cudaGetSymbolAddress(&pWc1hi, g_Wc1hi); cudaGetSymbolAddress(&pWc1lo, g_Wc1lo);
    cudaGetSymbolAddress(&pW1hi, g_W1hi); cudaGetSymbolAddress(&pW1lo, g_W1lo);
    cudaGetSymbolAddress(&pW2hi, g_W2hi); cudaGetSymbolAddress(&pW2lo, g_W2lo);
    cudaGetSymbolAddress(&pH1hi, g_H1hi); cudaGetSymbolAddress(&pH1lo, g_H1lo);
    cudaGetSymbolAddress(&pC2, g_cin2s);  cudaGetSymbolAddress(&pH2, g_h2);

    // launches 1-3 are x1's dependencies; x1 is launch #4 (ncu captures #4)
    prep_kernel<<<(NPAIR * Hq + 255) / 256, 256>>>(W0);
    pack_wsymT<<<(Hq * KPP_X1 + 255) / 256, 256>>>();
    gather_kernel<<<(Bq * Fq * (Dq / 4) + 255) / 256, 256>>>(sparse, E);

    x1s_mma_kernel<<<Bq / 4, 256, X1_SMEM>>>();

    lin_kernel<<<(Bq + 255) / 256, 256>>>(sparse, w_lin, b_lin);
    packB_T<<<(Hq * KP_CIN2 + 255) / 256, 256>>>(
        Wc1, Fq * Hq, Hq, KP_CIN2, Hq, (u32*)pWc1hi, (u32*)pWc1lo);
    packB_T<<<(512 * KP_MLP1 + 255) / 256, 256>>>(
        W1, Fq * Dq, Uq, KP_MLP1, 512, (u32*)pW1hi, (u32*)pW1lo);
    packB_T<<<(512 * KP_MLP2 + 255) / 256, 256>>>(
        W2, Uq, Uq, KP_MLP2, 512, (u32*)pW2hi, (u32*)pW2lo);

    // cin2 = S @ Wc1, split-K x2 in one launch (grid.z = 2, 128 blocks)
    gemm_pk<<<dim3(1, Bq / 128, 2), 256, G_SMEM>>>(
        (const u32*)pShi, (const u32*)pSlo, KP_CIN2,
        (const u32*)pWc1hi, (const u32*)pWc1lo, KP_CIN2, Hq,
        KP_SPLIT, Bq, nullptr, 0, (float*)pC2, nullptr, nullptr);
    // h1 = relu(embed @ W1 + b1) -> packed split only
    gemm_pk<<<dim3((Uq + 127) / 128, Bq / 128, 1), 256, G_SMEM>>>(
        (const u32*)pEhi, (const u32*)pElo, KP_MLP1,
        (const u32*)pW1hi, (const u32*)pW1lo, KP_MLP1, Uq,
        KP_MLP1, Bq, b1, 1, nullptr, (u32*)pH1hi, (u32*)pH1lo);
    // h2 = relu(h1 @ W2 + b2) -> fp32
    gemm_pk<<<dim3((Uq + 127) / 128, Bq / 128, 1), 256, G_SMEM>>>(
        (const u32*)pH1hi, (const u32*)pH1lo, KP_MLP2,
        (const u32*)pW2hi, (const u32*)pW2lo, KP_MLP2, Uq,
        KP_MLP2, Bq, b2, 1, (float*)pH2, nullptr, nullptr);

    final_kernel<<<(Bq * 32 + 255) / 256, 256>>>(dense, w_out, b_out, out);
}

// round 10
// speedup vs baseline: 1.5791x; 1.1647x over previous
#include <cuda_runtime.h>
#include <cuda_bf16.h>
#include <math.h>
#include <stdint.h>

#define Bq 8192
#define Fq 26
#define Dq 32
#define Vq 100000
#define Hq 128
#define NPAIR 351
#define KPAD 352       // padded pair count (x1 mma K)
#define KPP_X1 176     // KPAD/2
#define Uq 400
#define KP_CIN2 1664   // 3328/2
#define KP_SPLIT 832   // half of KP_CIN2
#define KP_MLP1 416    // 832/2
#define KP_MLP2 200    // 400/2

typedef unsigned u32;

// ---------------- scratch (no cudaMalloc allowed) ----------------
__device__ float g_wsym[NPAIR * Hq];
__device__ int   g_pij[KPAD];
__device__ __align__(16) u32 g_wBh[Hq * KPP_X1], g_wBl[Hq * KPP_X1];         // n-major [h][kp]
__device__ __align__(16) float g_embed[Bq * Fq * Dq];
__device__ __align__(16) u32 g_Ehi[Bq * KP_MLP1], g_Elo[Bq * KP_MLP1];       // A [m][kp]
__device__ __align__(16) u32 g_Shi[(size_t)Bq * KP_CIN2], g_Slo[(size_t)Bq * KP_CIN2];
__device__ __align__(16) u32 g_Wc1hi[Hq * KP_CIN2], g_Wc1lo[Hq * KP_CIN2];   // n-major [n][kp]
__device__ __align__(16) u32 g_W1hi[512 * KP_MLP1], g_W1lo[512 * KP_MLP1];   // n-major padded
__device__ __align__(16) u32 g_W2hi[512 * KP_MLP2], g_W2lo[512 * KP_MLP2];
__device__ __align__(16) u32 g_H1hi[Bq * KP_MLP2], g_H1lo[Bq * KP_MLP2];     // A [m][kp]
__device__ float g_lin[Bq];
__device__ float g_cin1[Bq * Hq];
__device__ float g_cin2s[2 * Bq * Hq];
__device__ float g_h2[Bq * Uq];

// ---------------- helpers ----------------
__device__ __forceinline__ void split2(float x, float y, u32 &hi, u32 &lo) {
    u32 xh = (u32)__bfloat16_as_ushort(__float2bfloat16_rn(x));
    u32 yh = (u32)__bfloat16_as_ushort(__float2bfloat16_rn(y));
    float xr = x - __uint_as_float(xh << 16);
    float yr = y - __uint_as_float(yh << 16);
    u32 xl = (u32)__bfloat16_as_ushort(__float2bfloat16_rn(xr));
    u32 yl = (u32)__bfloat16_as_ushort(__float2bfloat16_rn(yr));
    hi = xh | (yh << 16);
    lo = xl | (yl << 16);
}
__device__ __forceinline__ void mma16816(float c[4], const u32 a[4], u32 b0, u32 b1) {
    asm volatile(
        "mma.sync.aligned.m16n8k16.row.col.f32.bf16.bf16.f32 "
        "{%0,%1,%2,%3}, {%4,%5,%6,%7}, {%8,%9}, {%0,%1,%2,%3};"
        : "+f"(c[0]), "+f"(c[1]), "+f"(c[2]), "+f"(c[3])
        : "r"(a[0]), "r"(a[1]), "r"(a[2]), "r"(a[3]), "r"(b0), "r"(b1));
}
__device__ __forceinline__ void ldsm4(u32 &r0, u32 &r1, u32 &r2, u32 &r3, u32 addr) {
    asm volatile("ldmatrix.sync.aligned.m8n8.x4.shared.b16 {%0,%1,%2,%3}, [%4];"
                 : "=r"(r0), "=r"(r1), "=r"(r2), "=r"(r3) : "r"(addr));
}
__device__ __forceinline__ void ldsm4t(u32 &r0, u32 &r1, u32 &r2, u32 &r3, u32 addr) {
    asm volatile("ldmatrix.sync.aligned.m8n8.x4.trans.shared.b16 {%0,%1,%2,%3}, [%4];"
                 : "=r"(r0), "=r"(r1), "=r"(r2), "=r"(r3) : "r"(addr));
}
__device__ __forceinline__ u32 smem_u32(const void* p) {
    u32 a;
    asm("{ .reg .u64 t; cvta.to.shared.u64 t, %1; cvt.u32.u64 %0, t; }"
        : "=r"(a) : "l"(p));
    return a;
}

// ---------------- prep1: symmetrize W_cin0 ----------------
__global__ void prep_kernel(const float* __restrict__ W0) {
    int t = blockIdx.x * blockDim.x + threadIdx.x;
    if (t == 0) g_pij[NPAIR] = 0;
    if (t >= NPAIR * Hq) return;
    int p = t >> 7, h = t & 127;
    int i = 0, rem = p;
    while (rem >= Fq - i) { rem -= Fq - i; i++; }
    int j = i + rem;
    float w = W0[(i * Fq + j) * Hq + h];
    if (i != j) w += W0[(j * Fq + i) * Hq + h];
    g_wsym[t] = w;
    if (h == 0) g_pij[p] = i | (j << 8);
}

// ---------------- prep2: wsym -> n-major packed planes [h][kp] ----------------
__global__ void pack_wsymT() {
    int t = blockIdx.x * blockDim.x + threadIdx.x;
    if (t >= Hq * KPP_X1) return;
    int h = t / KPP_X1, kp = t % KPP_X1;
    float w0 = (2 * kp < NPAIR) ? g_wsym[(2 * kp) * Hq + h] : 0.f;
    float w1 = (2 * kp + 1 < NPAIR) ? g_wsym[(2 * kp + 1) * Hq + h] : 0.f;
    split2(w0, w1, g_wBh[t], g_wBl[t]);
}

// ---------------- packB_T: fp32 W[K][N] -> n-major packed [Npad][Kpp] ----------------
__global__ void packB_T(const float* __restrict__ W, int Kreal, int Nreal,
                        int Kpp, int Npad, u32* __restrict__ Oh, u32* __restrict__ Ol) {
    int t = blockIdx.x * blockDim.x + threadIdx.x;
    if (t >= Npad * Kpp) return;
    int n = t / Kpp, kp = t % Kpp;
    float f0 = (n < Nreal && 2 * kp < Kreal) ? W[(size_t)(2 * kp) * Nreal + n] : 0.f;
    float f1 = (n < Nreal && 2 * kp + 1 < Kreal) ? W[(size_t)(2 * kp + 1) * Nreal + n] : 0.f;
    split2(f0, f1, Oh[t], Ol[t]);
}

// ---------------- gather: fp32 embed + packed split for MLP1 ----------------
__global__ void gather_kernel(const int* __restrict__ idx, const float* __restrict__ E) {
    int e = blockIdx.x * blockDim.x + threadIdx.x;
    if (e >= Bq * Fq * (Dq / 4)) return;
    int q = e & 7;
    int r = e >> 3;
    int i = r % Fq;
    int b = r / Fq;
    int v = __ldg(&idx[b * Fq + i]);
    float4 val = __ldg((const float4*)(E + ((size_t)i * Vq + v) * Dq) + q);
    ((float4*)g_embed)[e] = val;
    int u = b * KP_MLP1 + (i * 8 + q) * 2;
    split2(val.x, val.y, g_Ehi[u],     g_Elo[u]);
    split2(val.z, val.w, g_Ehi[u + 1], g_Elo[u + 1]);
}

// ---------------- linear term ----------------
__global__ void lin_kernel(const int* __restrict__ idx, const float* __restrict__ w_lin,
                           const float* __restrict__ b_lin) {
    int b = blockIdx.x * blockDim.x + threadIdx.x;
    if (b >= Bq) return;
    float a = b_lin[0];
#pragma unroll
    for (int f = 0; f < Fq; f++) a += (float)idx[b * Fq + f] * w_lin[f];
    g_lin[b] = a;
}

// ---------------- fused x1 GEMM + tensor-core S/cin1 epilogue ----------------
// block = 4 batch rows; M = 128 (m = bl*32+d), N = 128, K = 352 (22 tiles).
// dyn smem (bytes):
//   mainloop stages: [0,6144) Ahi | [6144,12288) Alo | [12288,18432) Bh | [18432,24576) Bl
//   epilogue overlay: [0,34816) x1 hi plane (u16 [m][136]) | [34816,69632) x1 lo plane
//   E' planes: [69632,79872) EH (u32 [4*32][20]) | [79872,90112) EL
//   [90112,103424) sx | [103424,104832) spij
#define X1_SMEM 104832
__global__ __launch_bounds__(256, 2) void x1s_mma_kernel() {
    extern __shared__ char dsm_c[];
    u32*   Ahi  = (u32*)(dsm_c + 0);          // [128 m][12]
    u32*   Alo  = (u32*)(dsm_c + 6144);
    u32*   Bh_s = (u32*)(dsm_c + 12288);      // [128 n][12]
    u32*   Bl_s = (u32*)(dsm_c + 18432);
    u32*   XH   = (u32*)(dsm_c + 0);          // overlay: x1 hi plane, u32 [m][68]
    u32*   XL   = (u32*)(dsm_c + 34816);
    u32*   EH   = (u32*)(dsm_c + 69632);      // E' hi [4*32][20]
    u32*   EL   = (u32*)(dsm_c + 79872);
    float* sx   = (float*)(dsm_c + 90112);
    int*   spij = (int*)(dsm_c + 103424);

    int tid  = threadIdx.x;
    int warp = tid >> 5, lane = tid & 31;
    int gid  = lane >> 2, tg = lane & 3;
    int wm   = warp & 3, wn = warp >> 2;

    const float* eb = g_embed + (size_t)blockIdx.x * 4 * Fq * Dq;
    for (int e = tid; e < 4 * Fq * Dq; e += 256) sx[e] = eb[e];
    for (int e = tid; e < KPAD; e += 256) spij[e] = g_pij[e];

    float c[2][8][4];
#pragma unroll
    for (int mt = 0; mt < 2; mt++)
#pragma unroll
        for (int nt = 0; nt < 8; nt++)
#pragma unroll
            for (int r = 0; r < 4; r++) c[mt][nt][r] = 0.f;

    // ldmatrix per-lane offsets (u32 units, pitch 12)
    int la_off = ((lane & 7) + (lane & 8)) * 12 + ((lane & 16) >> 2);
    int lb_off = ((lane & 7) + ((lane & 16) >> 1)) * 12 + ((lane & 8) >> 1);
    u32 smA = smem_u32(dsm_c);
    u32 smB = smA + 12288;

    int bn = tid >> 1, bq = tid & 1;

    __syncthreads();

#pragma unroll 1
    for (int t = 0; t < 22; t++) {
#pragma unroll
        for (int it = 0; it < 4; it++) {      // build A tile 128 m x 8 kp
            int idx = it * 256 + tid;
            int kp = idx >> 7, m = idx & 127;
            int bl = m >> 5, d = m & 31;
            int k0 = t * 16 + kp * 2;
            int pij0 = spij[k0], pij1 = spij[k0 + 1];
            const float* sb = sx + bl * (Fq * Dq) + d;
            float a0 = sb[(pij0 & 255) * Dq] * sb[(pij0 >> 8) * Dq];
            float a1 = sb[(pij1 & 255) * Dq] * sb[(pij1 >> 8) * Dq];
            split2(a0, a1, Ahi[m * 12 + kp], Alo[m * 12 + kp]);
        }
        {   // stage B tile (n-major): 128 n x 8 kp, 1 uint4/thread/plane
            uint4 vh = *(const uint4*)&g_wBh[bn * KPP_X1 + t * 8 + bq * 4];
            uint4 vl = *(const uint4*)&g_wBl[bn * KPP_X1 + t * 8 + bq * 4];
            *(uint4*)&Bh_s[bn * 12 + bq * 4] = vh;
            *(uint4*)&Bl_s[bn * 12 + bq * 4] = vl;
        }
        __syncthreads();

        u32 ah[2][4], al[2][4];
#pragma unroll
        for (int mt = 0; mt < 2; mt++) {
            u32 ad = smA + ((wm * 32 + mt * 16) * 12 + la_off) * 4;
            ldsm4(ah[mt][0], ah[mt][1], ah[mt][2], ah[mt][3], ad);
            ldsm4(al[mt][0], al[mt][1], al[mt][2], al[mt][3], ad + 6144);
        }
#pragma unroll
        for (int np = 0; np < 4; np++) {
            u32 bd = smB + ((wn * 64 + np * 16) * 12 + lb_off) * 4;
            u32 bh[4], bl[4];
            ldsm4(bh[0], bh[1], bh[2], bh[3], bd);
            ldsm4(bl[0], bl[1], bl[2], bl[3], bd + 6144);
#pragma unroll
            for (int mt = 0; mt < 2; mt++) {
                mma16816(c[mt][2 * np],     ah[mt], bh[0], bh[1]);
                mma16816(c[mt][2 * np],     ah[mt], bl[0], bl[1]);
                mma16816(c[mt][2 * np],     al[mt], bh[0], bh[1]);
                mma16816(c[mt][2 * np + 1], ah[mt], bh[2], bh[3]);
                mma16816(c[mt][2 * np + 1], ah[mt], bl[2], bl[3]);
                mma16816(c[mt][2 * np + 1], al[mt], bh[2], bh[3]);
            }
        }
        __syncthreads();
    }

    // ---- build E' bf16 planes (reads sx; 27th row = ones for cin1) ----
#pragma unroll
    for (int it = 0; it < 8; it++) {
        int e = it * 256 + tid;               // 4*32*16 = 2048 entries
        int kp = e & 15;
        int i  = (e >> 4) & 31;
        int b4 = e >> 9;
        float f0 = 0.f, f1 = 0.f;
        if (i < Fq) {
            f0 = sx[b4 * (Fq * Dq) + i * Dq + 2 * kp];
            f1 = sx[b4 * (Fq * Dq) + i * Dq + 2 * kp + 1];
        } else if (i == Fq) {
            f0 = 1.f; f1 = 1.f;
        }
        u32 hi, lo;
        split2(f0, f1, hi, lo);
        EH[(b4 * 32 + i) * 20 + kp] = hi;
        EL[(b4 * 32 + i) * 20 + kp] = lo;
    }

    // ---- spill x1 as bf16 hi/lo planes [m][h] (u32-packed h-pairs, pitch 68 u32) ----
#pragma unroll
    for (int mt = 0; mt < 2; mt++) {
        int r0 = wm * 32 + mt * 16 + gid;
#pragma unroll
        for (int nt = 0; nt < 8; nt++) {
            int hp = (wn * 64 + nt * 8 + 2 * tg) >> 1;
            u32 hi, lo;
            split2(c[mt][nt][0], c[mt][nt][1], hi, lo);
            XH[r0 * 68 + hp] = hi;
            XL[r0 * 68 + hp] = lo;
            split2(c[mt][nt][2], c[mt][nt][3], hi, lo);
            XH[(r0 + 8) * 68 + hp] = hi;
            XL[(r0 + 8) * 68 + hp] = lo;
        }
    }
    __syncthreads();

    // ---- S-mma: S[b4] = E'[32x32] x x1[32x128]; warp = (b4, h-half) ----
    int bRow0 = blockIdx.x * 4;
    int wn2 = warp & 1, b4w = warp >> 1;
    int b = bRow0 + b4w;

    float c2[2][8][4];
#pragma unroll
    for (int mt = 0; mt < 2; mt++)
#pragma unroll
        for (int nt = 0; nt < 8; nt++)
#pragma unroll
            for (int r = 0; r < 4; r++) c2[mt][nt][r] = 0.f;

    u32 smEH = smem_u32(dsm_c) + 69632;
    u32 smXH = smem_u32(dsm_c);
    int la2 = ((lane & 7) + (lane & 8)) * 20 + ((lane & 16) >> 2);
    // trans-B per-lane byte offset: row k = lane&15, col-octet from bit4
    int lb2_bytes = (lane & 15) * 272 + ((lane & 16) >> 4) * 16;

#pragma unroll
    for (int kt = 0; kt < 2; kt++) {
        u32 aH[2][4], aL[2][4];
#pragma unroll
        for (int mt = 0; mt < 2; mt++) {
            u32 ad = smEH + ((b4w * 32 + mt * 16) * 20 + kt * 8 + la2) * 4;
            ldsm4(aH[mt][0], aH[mt][1], aH[mt][2], aH[mt][3], ad);
            ldsm4(aL[mt][0], aL[mt][1], aL[mt][2], aL[mt][3], ad + 10240);
        }
#pragma unroll
        for (int ng = 0; ng < 4; ng++) {
            u32 badr = smXH + (b4w * 32 + kt * 16) * 272
                     + (wn2 * 64 + ng * 16) * 2 + lb2_bytes;
            u32 bh[4], bl[4];
            ldsm4t(bh[0], bh[1], bh[2], bh[3], badr);
            ldsm4t(bl[0], bl[1], bl[2], bl[3], badr + 34816);
#pragma unroll
            for (int mt = 0; mt < 2; mt++) {
                mma16816(c2[mt][2 * ng],     aH[mt], bh[0], bh[1]);
                mma16816(c2[mt][2 * ng],     aH[mt], bl[0], bl[1]);
                mma16816(c2[mt][2 * ng],     aL[mt], bh[0], bh[1]);
                mma16816(c2[mt][2 * ng + 1], aH[mt], bh[2], bh[3]);
                mma16816(c2[mt][2 * ng + 1], aH[mt], bl[2], bl[3]);
                mma16816(c2[mt][2 * ng + 1], aL[mt], bh[2], bh[3]);
            }
        }
    }

    // ---- write S (packed) + cin1 (ones row, i == 26) ----
#pragma unroll
    for (int mt = 0; mt < 2; mt++) {
#pragma unroll
        for (int nt = 0; nt < 8; nt++) {
            int h  = wn2 * 64 + nt * 8 + 2 * tg;
            int hp = h >> 1;
            int i1 = mt * 16 + gid;          // always < 26
            int i2 = i1 + 8;
            u32 hi, lo;
            split2(c2[mt][nt][0], c2[mt][nt][1], hi, lo);
            g_Shi[(size_t)b * KP_CIN2 + i1 * 64 + hp] = hi;
            g_Slo[(size_t)b * KP_CIN2 + i1 * 64 + hp] = lo;
            if (i2 < Fq) {
                split2(c2[mt][nt][2], c2[mt][nt][3], hi, lo);
                g_Shi[(size_t)b * KP_CIN2 + i2 * 64 + hp] = hi;
                g_Slo[(size_t)b * KP_CIN2 + i2 * 64 + hp] = lo;
            } else if (i2 == Fq) {
                g_cin1[b * Hq + h]     = c2[mt][nt][2];
                g_cin1[b * Hq + h + 1] = c2[mt][nt][3];
            }
        }
    }
}

// ---------------- packed GEMM (ldmatrix + split-K via blockIdx.z) ----------------
// BM=128, BN=128, BK=16 (8 kp); A [M][pitchA] row-major, B n-major [Npad][pitchB].
#define G_SMEM 49152
__global__ __launch_bounds__(256) void gemm_pk(
    const u32* __restrict__ Agh, const u32* __restrict__ Agl, int pitchA,
    const u32* __restrict__ Bgh, const u32* __restrict__ Bgl, int pitchB, int N,
    int kpSeg, int Mtot,
    const float* __restrict__ bias, int relu,
    float* __restrict__ Cf, u32* __restrict__ Ch, u32* __restrict__ Cl)
{
    extern __shared__ char dsm_c[];
    u32* dsm = (u32*)dsm_c;
    int tid  = threadIdx.x;
    int warp = tid >> 5, lane = tid & 31;
    int gid  = lane >> 2, tg = lane & 3;
    int wm   = warp & 3, wn = warp >> 2;
    int m0 = blockIdx.y * 128, n0 = blockIdx.x * 128;
    int kpOff = blockIdx.z * kpSeg;
    if (Cf) Cf += (size_t)blockIdx.z * Mtot * N;

    int sr = tid >> 1, sq = tid & 1;
    const u32* pAh = Agh + (size_t)(m0 + sr) * pitchA + kpOff + sq * 4;
    const u32* pAl = Agl + (size_t)(m0 + sr) * pitchA + kpOff + sq * 4;
    const u32* pBh = Bgh + (size_t)(n0 + sr) * pitchB + kpOff + sq * 4;
    const u32* pBl = Bgl + (size_t)(n0 + sr) * pitchB + kpOff + sq * 4;
    int sidx = sr * 12 + sq * 4;

    int la_off = ((lane & 7) + (lane & 8)) * 12 + ((lane & 16) >> 2);
    int lb_off = ((lane & 7) + ((lane & 16) >> 1)) * 12 + ((lane & 8) >> 1);
    u32 smbase = smem_u32(dsm_c);

    float c[2][8][4];
#pragma unroll
    for (int mt = 0; mt < 2; mt++)
#pragma unroll
        for (int nt = 0; nt < 8; nt++)
#pragma unroll
            for (int r = 0; r < 4; r++) c[mt][nt][r] = 0.f;

    int T = kpSeg >> 3;
    {   // prologue: stage tile 0 into buf 0
        uint4 xah = *(const uint4*)pAh;
        uint4 xal = *(const uint4*)pAl;
        uint4 xbh = *(const uint4*)pBh;
        uint4 xbl = *(const uint4*)pBl;
        *(uint4*)&dsm[sidx]        = xah;
        *(uint4*)&dsm[3072 + sidx] = xal;
        *(uint4*)&dsm[6144 + sidx] = xbh;
        *(uint4*)&dsm[9216 + sidx] = xbl;
    }
    __syncthreads();
    int buf = 0;

#pragma unroll 1
    for (int t = 0; t < T; t++) {
        uint4 xah, xal, xbh, xbl;
        bool have = (t + 1 < T);
        if (have) {
            int o = (t + 1) * 8;
            xah = *(const uint4*)(pAh + o);
            xal = *(const uint4*)(pAl + o);
            xbh = *(const uint4*)(pBh + o);
            xbl = *(const uint4*)(pBl + o);
        }

        u32 aBase = smbase + (buf * 1536) * 4;
        u32 bBase = smbase + ((6144 + buf * 1536)) * 4;
        u32 ah[2][4], al[2][4];
#pragma unroll
        for (int mt = 0; mt < 2; mt++) {
            u32 ad = aBase + ((wm * 32 + mt * 16) * 12 + la_off) * 4;
            ldsm4(ah[mt][0], ah[mt][1], ah[mt][2], ah[mt][3], ad);
            ldsm4(al[mt][0], al[mt][1], al[mt][2], al[mt][3], ad + 3072 * 4);
        }
#pragma unroll
        for (int np = 0; np < 4; np++) {
            u32 bd = bBase + ((wn * 64 + np * 16) * 12 + lb_off) * 4;
            u32 bh[4], bl[4];
            ldsm4(bh[0], bh[1], bh[2], bh[3], bd);
            ldsm4(bl[0], bl[1], bl[2], bl[3], bd + 3072 * 4);
#pragma unroll
            for (int mt = 0; mt < 2; mt++) {
                mma16816(c[mt][2 * np],     ah[mt], bh[0], bh[1]);
                mma16816(c[mt][2 * np],     ah[mt], bl[0], bl[1]);
                mma16816(c[mt][2 * np],     al[mt], bh[0], bh[1]);
                mma16816(c[mt][2 * np + 1], ah[mt], bh[2], bh[3]);
                mma16816(c[mt][2 * np + 1], ah[mt], bl[2], bl[3]);
                mma16816(c[mt][2 * np + 1], al[mt], bh[2], bh[3]);
            }
        }

        if (have) {
            int nb = buf ^ 1;
            *(uint4*)&dsm[nb * 1536 + sidx]        = xah;
            *(uint4*)&dsm[3072 + nb * 1536 + sidx] = xal;
            *(uint4*)&dsm[6144 + nb * 1536 + sidx] = xbh;
            *(uint4*)&dsm[9216 + nb * 1536 + sidx] = xbl;
            __syncthreads();
            buf = nb;
        }
    }

    // epilogue
    int Np = N >> 1;
#pragma unroll
    for (int mt = 0; mt < 2; mt++) {
        int r0 = m0 + wm * 32 + mt * 16 + gid;
#pragma unroll
        for (int nt = 0; nt < 8; nt++) {
            int col = n0 + wn * 64 + nt * 8 + 2 * tg;
            if (col >= N) continue;
            float b0v = bias ? bias[col] : 0.f;
            float b1v = bias ? bias[col + 1] : 0.f;
            float v0 = c[mt][nt][0] + b0v, v1 = c[mt][nt][1] + b1v;
            float v2 = c[mt][nt][2] + b0v, v3 = c[mt][nt][3] + b1v;
            if (relu) {
                v0 = fmaxf(v0, 0.f); v1 = fmaxf(v1, 0.f);
                v2 = fmaxf(v2, 0.f); v3 = fmaxf(v3, 0.f);
            }
            if (Cf) {
                *(float2*)&Cf[(size_t)r0 * N + col]       = make_float2(v0, v1);
                *(float2*)&Cf[(size_t)(r0 + 8) * N + col] = make_float2(v2, v3);
            }
            if (Ch) {
                u32 hi, lo;
                split2(v0, v1, hi, lo);
                Ch[(size_t)r0 * Np + (col >> 1)] = hi;
                Cl[(size_t)r0 * Np + (col >> 1)] = lo;
                split2(v2, v3, hi, lo);
                Ch[(size_t)(r0 + 8) * Np + (col >> 1)] = hi;
                Cl[(size_t)(r0 + 8) * Np + (col >> 1)] = lo;
            }
        }
    }
}

// ---------------- final head ----------------
__global__ void final_kernel(const float* __restrict__ dense,
                             const float* __restrict__ w_out,
                             const float* __restrict__ b_out,
                             float* __restrict__ out) {
    int gt = blockIdx.x * blockDim.x + threadIdx.x;
    int b = gt >> 5, lane = gt & 31;
    if (b >= Bq) return;
    float a = 0.f;
    const float* c1 = g_cin1 + b * Hq;
    const float* c2a = g_cin2s + b * Hq;
    const float* c2b = g_cin2s + Bq * Hq + b * Hq;
    const float* hh = g_h2 + b * Uq;
    for (int t = lane; t < Hq; t += 32) a += c1[t] * w_out[1 + t];
    for (int t = lane; t < Hq; t += 32) a += (c2a[t] + c2b[t]) * w_out[1 + Hq + t];
    for (int t = lane; t < Uq; t += 32) a += hh[t] * w_out[1 + 2 * Hq + t];
    if (lane < 13) a += dense[b * 13 + lane] * w_out[1 + 2 * Hq + Uq + lane];
#pragma unroll
    for (int o = 16; o > 0; o >>= 1) a += __shfl_down_sync(0xffffffffu, a, o);
    if (lane == 0) {
        float tot = a + g_lin[b] * w_out[0] + b_out[0];
        float o;
        if (tot >= 0.f) { o = 1.f / (1.f + expf(-tot)); }
        else            { float e = expf(tot); o = e / (1.f + e); }
        out[b] = o;
    }
}

extern "C" void kernel_launch(void* const* d_in, const int* in_sizes, int n_in,
                              void* d_out, int out_size) {
    (void)in_sizes; (void)n_in; (void)out_size;
    const float* dense  = (const float*)d_in[0];
    const int*   sparse = (const int*)  d_in[1];
    const float* E      = (const float*)d_in[2];
    const float* W0     = (const float*)d_in[3];
    const float* Wc1    = (const float*)d_in[4];
    const float* W1     = (const float*)d_in[5];
    const float* b1     = (const float*)d_in[6];
    const float* W2     = (const float*)d_in[7];
    const float* b2     = (const float*)d_in[8];
    const float* w_lin  = (const float*)d_in[9];
    const float* b_lin  = (const float*)d_in[10];
    const float* w_out  = (const float*)d_in[11];
    const float* b_out  = (const float*)d_in[12];
    float* out = (float*)d_out;

    static int smem_set = 0;
    if (!smem_set) {
        cudaFuncSetAttribute(x1s_mma_kernel,
                             cudaFuncAttributeMaxDynamicSharedMemorySize, X1_SMEM);
        cudaFuncSetAttribute(gemm_pk,
                             cudaFuncAttributeMaxDynamicSharedMemorySize, G_SMEM);
        smem_set = 1;
    }

    void *pShi, *pSlo, *pEhi, *pElo, *pWc1hi, *pWc1lo, *pW1hi, *pW1lo,
         *pW2hi, *pW2lo, *pH1hi, *pH1lo, *pC2, *pH2;
    cudaGetSymbolAddress(&pShi, g_Shi);   cudaGetSymbolAddress(&pSlo, g_Slo);
    cudaGetSymbolAddress(&pEhi, g_Ehi);   cudaGetSymbolAddress(&pElo, g_Elo);
    cudaGetSymbolAddress(&pWc1hi, g_Wc1hi); cudaGetSymbolAddress(&pWc1lo, g_Wc1lo);
    cudaGetSymbolAddress(&pW1hi, g_W1hi); cudaGetSymbolAddress(&pW1lo, g_W1lo);
    cudaGetSymbolAddress(&pW2hi, g_W2hi); cudaGetSymbolAddress(&pW2lo, g_W2lo);
    cudaGetSymbolAddress(&pH1hi, g_H1hi); cudaGetSymbolAddress(&pH1lo, g_H1lo);
    cudaGetSymbolAddress(&pC2, g_cin2s);  cudaGetSymbolAddress(&pH2, g_h2);

    // launches 1-3 are x1's dependencies; x1 is launch #4 (ncu captures #4)
    prep_kernel<<<(NPAIR * Hq + 255) / 256, 256>>>(W0);
    pack_wsymT<<<(Hq * KPP_X1 + 255) / 256, 256>>>();
    gather_kernel<<<(Bq * Fq * (Dq / 4) + 255) / 256, 256>>>(sparse, E);

    x1s_mma_kernel<<<Bq / 4, 256, X1_SMEM>>>();

    lin_kernel<<<(Bq + 255) / 256, 256>>>(sparse, w_lin, b_lin);
    packB_T<<<(Hq * KP_CIN2 + 255) / 256, 256>>>(
        Wc1, Fq * Hq, Hq, KP_CIN2, Hq, (u32*)pWc1hi, (u32*)pWc1lo);
    packB_T<<<(512 * KP_MLP1 + 255) / 256, 256>>>(
        W1, Fq * Dq, Uq, KP_MLP1, 512, (u32*)pW1hi, (u32*)pW1lo);
    packB_T<<<(512 * KP_MLP2 + 255) / 256, 256>>>(
        W2, Uq, Uq, KP_MLP2, 512, (u32*)pW2hi, (u32*)pW2lo);

    // cin2 = S @ Wc1, split-K x2 in one launch (grid.z = 2, 128 blocks)
    gemm_pk<<<dim3(1, Bq / 128, 2), 256, G_SMEM>>>(
        (const u32*)pShi, (const u32*)pSlo, KP_CIN2,
        (const u32*)pWc1hi, (const u32*)pWc1lo, KP_CIN2, Hq,
        KP_SPLIT, Bq, nullptr, 0, (float*)pC2, nullptr, nullptr);
    // h1 = relu(embed @ W1 + b1) -> packed split only
    gemm_pk<<<dim3((Uq + 127) / 128, Bq / 128, 1), 256, G_SMEM>>>(
        (const u32*)pEhi, (const u32*)pElo, KP_MLP1,
        (const u32*)pW1hi, (const u32*)pW1lo, KP_MLP1, Uq,
        KP_MLP1, Bq, b1, 1, nullptr, (u32*)pH1hi, (u32*)pH1lo);
    // h2 = relu(h1 @ W2 + b2) -> fp32
    gemm_pk<<<dim3((Uq + 127) / 128, Bq / 128, 1), 256, G_SMEM>>>(
        (const u32*)pH1hi, (const u32*)pH1lo, KP_MLP2,
        (const u32*)pW2hi, (const u32*)pW2lo, KP_MLP2, Uq,
        KP_MLP2, Bq, b2, 1, (float*)pH2, nullptr, nullptr);

    final_kernel<<<(Bq * 32 + 255) / 256, 256>>>(dense, w_out, b_out, out);
}